// round 1
// baseline (speedup 1.0000x reference)
#include <cuda_runtime.h>
#include <cstdint>

// Problem constants
constexpr int Bb = 4;
constexpr int Tt = 2048;
constexpr int Cc = 1024;
constexpr int Hh = 16;
constexpr int HD = 64;          // head dim
constexpr int BT = Bb * Tt;     // 8192 rows

// Scratch (device globals: the allowed allocation-free scratch path)
__device__ float g_q[(size_t)Bb * Hh * Tt * HD];   // (B,H,T,HD), pre-scaled by 1/sqrt(HD)
__device__ float g_k[(size_t)Bb * Hh * Tt * HD];
__device__ float g_v[(size_t)Bb * Hh * Tt * HD];
__device__ float g_y[(size_t)Bb * Tt * Cc];        // attention output (B,T,C)

// ---------------------------------------------------------------------------
// Tiled GEMM: 128x128 tile, BK=16, 256 threads, 8x8 register block per thread.
// MODE 0: A = x (param), C scattered into g_q/g_k/g_v with q pre-scaled.
// MODE 1: A = g_y,       C = out + bias.
// K is fixed at 1024 for both uses.
// ---------------------------------------------------------------------------
template <int MODE>
__global__ __launch_bounds__(256) void sa_gemm128(
    const float* __restrict__ Ain, const float* __restrict__ W,
    const float* __restrict__ bias, float* __restrict__ out, int N)
{
    constexpr int K = 1024;
    __shared__ float As[16][132];   // A tile transposed [k][m], padded
    __shared__ float Bs[16][128];   // B tile [k][n]

    const float* A = (MODE == 0) ? Ain : (const float*)g_y;
    int tid = threadIdx.x;
    int m0 = blockIdx.y * 128;
    int n0 = blockIdx.x * 128;
    int tm = tid >> 4;
    int tn = tid & 15;

    float acc[8][8];
#pragma unroll
    for (int i = 0; i < 8; i++)
#pragma unroll
        for (int j = 0; j < 8; j++) acc[i][j] = 0.0f;

    for (int k0 = 0; k0 < K; k0 += 16) {
        // Load A tile (128 rows x 16 k), store transposed
#pragma unroll
        for (int it = 0; it < 2; it++) {
            int f = tid + it * 256;           // 512 float4s
            int row = f >> 2, cg = f & 3;
            float4 v = *reinterpret_cast<const float4*>(
                A + (size_t)(m0 + row) * K + k0 + cg * 4);
            As[cg * 4 + 0][row] = v.x;
            As[cg * 4 + 1][row] = v.y;
            As[cg * 4 + 2][row] = v.z;
            As[cg * 4 + 3][row] = v.w;
        }
        // Load B tile (16 k x 128 n)
#pragma unroll
        for (int it = 0; it < 2; it++) {
            int f = tid + it * 256;
            int row = f >> 5, cg = f & 31;
            *reinterpret_cast<float4*>(&Bs[row][cg * 4]) =
                *reinterpret_cast<const float4*>(
                    W + (size_t)(k0 + row) * N + n0 + cg * 4);
        }
        __syncthreads();

#pragma unroll
        for (int kk = 0; kk < 16; kk++) {
            float a[8], b[8];
            *reinterpret_cast<float4*>(a)     = *reinterpret_cast<float4*>(&As[kk][tm * 8]);
            *reinterpret_cast<float4*>(a + 4) = *reinterpret_cast<float4*>(&As[kk][tm * 8 + 4]);
            *reinterpret_cast<float4*>(b)     = *reinterpret_cast<float4*>(&Bs[kk][tn * 8]);
            *reinterpret_cast<float4*>(b + 4) = *reinterpret_cast<float4*>(&Bs[kk][tn * 8 + 4]);
#pragma unroll
            for (int i = 0; i < 8; i++)
#pragma unroll
                for (int j = 0; j < 8; j++)
                    acc[i][j] = fmaf(a[i], b[j], acc[i][j]);
        }
        __syncthreads();
    }

    if (MODE == 0) {
        // Scatter into q/k/v with layout (B,H,T,HD); q gets 1/sqrt(64) = 0.125
#pragma unroll
        for (int i = 0; i < 8; i++) {
            int m = m0 + tm * 8 + i;
            int bidx = m >> 11;            // / 2048
            int t = m & 2047;
#pragma unroll
            for (int jg = 0; jg < 2; jg++) {
                int n = n0 + tn * 8 + jg * 4;
                int part = n >> 10;        // 0=q 1=k 2=v
                int c = n & 1023;
                int h = c >> 6;
                int d = c & 63;
                float* dst = (part == 0) ? g_q : (part == 1) ? g_k : g_v;
                float sc = (part == 0) ? 0.125f : 1.0f;
                float4 v;
                v.x = acc[i][jg * 4 + 0] * sc;
                v.y = acc[i][jg * 4 + 1] * sc;
                v.z = acc[i][jg * 4 + 2] * sc;
                v.w = acc[i][jg * 4 + 3] * sc;
                size_t idx = ((((size_t)bidx * Hh + h) * Tt + t) * HD + d);
                *reinterpret_cast<float4*>(dst + idx) = v;
            }
        }
    } else {
#pragma unroll
        for (int i = 0; i < 8; i++) {
            int m = m0 + tm * 8 + i;
#pragma unroll
            for (int jg = 0; jg < 2; jg++) {
                int n = n0 + tn * 8 + jg * 4;
                float4 bv = *reinterpret_cast<const float4*>(bias + n);
                float4 v;
                v.x = acc[i][jg * 4 + 0] + bv.x;
                v.y = acc[i][jg * 4 + 1] + bv.y;
                v.z = acc[i][jg * 4 + 2] + bv.z;
                v.w = acc[i][jg * 4 + 3] + bv.w;
                *reinterpret_cast<float4*>(out + (size_t)m * N + n) = v;
            }
        }
    }
}

// ---------------------------------------------------------------------------
// Flash attention, 64x64 tiles, 256 threads, 4x4 register block per thread.
// Causal: CTA (qt, bh) loops kt = 0..qt only. Online softmax via 16-lane
// shuffle reductions (rows live in 16 consecutive lanes).
// Smem = exactly 48KB static: Qs(16K) + KPs(16K, K-tile then reused for P) +
// Vs(16K). K tile stored with a float4-group XOR swizzle so the n-strided
// reads in S = Q*K^T are bank-spread.
// ---------------------------------------------------------------------------
__global__ __launch_bounds__(256, 2) void sa_attn64(const int* __restrict__ pad)
{
    __shared__ float Qs[64 * 64];
    __shared__ float KPs[64 * 64];   // K tile (swizzled), later reused as P [r][c]
    __shared__ float Vs[64 * 64];

    int tid = threadIdx.x;
    int qt = (int)gridDim.x - 1 - (int)blockIdx.x;   // big tiles scheduled first
    int bh = blockIdx.y;
    int bb = bh >> 4;
    int hh = bh & 15;
    int q0 = qt * 64;

    size_t base = (size_t)bh * Tt * HD;
    const float* Qg = g_q + base;
    const float* Kg = g_k + base;
    const float* Vg = g_v + base;

    int r0 = (tid >> 4) * 4;     // 4 output rows owned
    int c0 = (tid & 15) * 4;     // 4 output cols owned

    // Load Q tile once (rows q0..q0+63), natural layout [row][d]
#pragma unroll
    for (int it = 0; it < 4; it++) {
        int f = tid + it * 256;
        int row = f >> 4, dq = f & 15;
        *reinterpret_cast<float4*>(&Qs[row * 64 + dq * 4]) =
            *reinterpret_cast<const float4*>(Qg + (size_t)(q0 + row) * 64 + dq * 4);
    }

    float o[4][4];
#pragma unroll
    for (int i = 0; i < 4; i++)
#pragma unroll
        for (int j = 0; j < 4; j++) o[i][j] = 0.0f;
    float mrow[4] = {-1e30f, -1e30f, -1e30f, -1e30f};
    float lrow[4] = {0.0f, 0.0f, 0.0f, 0.0f};

    for (int kt = 0; kt <= qt; kt++) {
        __syncthreads();   // prev O-GEMM reads done before K/V overwrite; Q ready on iter 0
        int k0 = kt * 64;
        // Load K (swizzled) and V (natural)
#pragma unroll
        for (int it = 0; it < 4; it++) {
            int f = tid + it * 256;
            int row = f >> 4, dq = f & 15;
            float4 kv = *reinterpret_cast<const float4*>(Kg + (size_t)(k0 + row) * 64 + dq * 4);
            float4 vv = *reinterpret_cast<const float4*>(Vg + (size_t)(k0 + row) * 64 + dq * 4);
            int dqs = dq ^ ((row >> 2) & 7);
            *reinterpret_cast<float4*>(&KPs[row * 64 + dqs * 4]) = kv;
            *reinterpret_cast<float4*>(&Vs[row * 64 + dq * 4]) = vv;
        }
        __syncthreads();

        // S = Q * K^T  (thread computes rows r0..r0+3 x cols c0..c0+3)
        float acc[4][4];
#pragma unroll
        for (int i = 0; i < 4; i++)
#pragma unroll
            for (int j = 0; j < 4; j++) acc[i][j] = 0.0f;

        int sw = (c0 >> 2) & 7;   // swizzle constant for this thread's K columns
#pragma unroll
        for (int dq = 0; dq < 16; dq++) {
            float4 q4[4], k4[4];
#pragma unroll
            for (int i = 0; i < 4; i++)
                q4[i] = *reinterpret_cast<float4*>(&Qs[(r0 + i) * 64 + dq * 4]);
            int dqs = (dq ^ sw) * 4;
#pragma unroll
            for (int j = 0; j < 4; j++)
                k4[j] = *reinterpret_cast<float4*>(&KPs[(c0 + j) * 64 + dqs]);
#pragma unroll
            for (int i = 0; i < 4; i++)
#pragma unroll
                for (int j = 0; j < 4; j++)
                    acc[i][j] = fmaf(q4[i].x, k4[j].x,
                                fmaf(q4[i].y, k4[j].y,
                                fmaf(q4[i].z, k4[j].z,
                                fmaf(q4[i].w, k4[j].w, acc[i][j]))));
        }

        // Mask: pad always; causal only on the diagonal tile
        bool diag = (kt == qt);
#pragma unroll
        for (int j = 0; j < 4; j++) {
            int pv = __ldg(&pad[bb * Tt + k0 + c0 + j]);
#pragma unroll
            for (int i = 0; i < 4; i++) {
                bool keep = (pv != 0) && (!diag || (r0 + i >= c0 + j));
                if (!keep) acc[i][j] = -1e30f;
            }
        }

        // Online softmax update (16-lane shuffle reductions per row)
#pragma unroll
        for (int i = 0; i < 4; i++) {
            float mt = fmaxf(fmaxf(acc[i][0], acc[i][1]), fmaxf(acc[i][2], acc[i][3]));
#pragma unroll
            for (int s = 1; s < 16; s <<= 1)
                mt = fmaxf(mt, __shfl_xor_sync(0xffffffffu, mt, s));
            float mnew = fmaxf(mrow[i], mt);
            float alpha = __expf(mrow[i] - mnew);
            float rs = 0.0f;
#pragma unroll
            for (int j = 0; j < 4; j++) {
                acc[i][j] = __expf(acc[i][j] - mnew);
                rs += acc[i][j];
            }
#pragma unroll
            for (int s = 1; s < 16; s <<= 1)
                rs += __shfl_xor_sync(0xffffffffu, rs, s);
            lrow[i] = lrow[i] * alpha + rs;
            mrow[i] = mnew;
#pragma unroll
            for (int j = 0; j < 4; j++) o[i][j] *= alpha;
        }

        __syncthreads();   // all S reads of KPs done -> safe to overwrite with P

        // Write P [r][c] into KPs (float4 per row-chunk)
#pragma unroll
        for (int i = 0; i < 4; i++) {
            float4 pv4 = {acc[i][0], acc[i][1], acc[i][2], acc[i][3]};
            *reinterpret_cast<float4*>(&KPs[(r0 + i) * 64 + c0]) = pv4;
        }
        __syncthreads();

        // O += P * V
#pragma unroll 8
        for (int jj = 0; jj < 64; jj++) {
            float4 v4 = *reinterpret_cast<float4*>(&Vs[jj * 64 + c0]);
            float p0 = KPs[(r0 + 0) * 64 + jj];
            float p1 = KPs[(r0 + 1) * 64 + jj];
            float p2 = KPs[(r0 + 2) * 64 + jj];
            float p3 = KPs[(r0 + 3) * 64 + jj];
            o[0][0] = fmaf(p0, v4.x, o[0][0]); o[0][1] = fmaf(p0, v4.y, o[0][1]);
            o[0][2] = fmaf(p0, v4.z, o[0][2]); o[0][3] = fmaf(p0, v4.w, o[0][3]);
            o[1][0] = fmaf(p1, v4.x, o[1][0]); o[1][1] = fmaf(p1, v4.y, o[1][1]);
            o[1][2] = fmaf(p1, v4.z, o[1][2]); o[1][3] = fmaf(p1, v4.w, o[1][3]);
            o[2][0] = fmaf(p2, v4.x, o[2][0]); o[2][1] = fmaf(p2, v4.y, o[2][1]);
            o[2][2] = fmaf(p2, v4.z, o[2][2]); o[2][3] = fmaf(p2, v4.w, o[2][3]);
            o[3][0] = fmaf(p3, v4.x, o[3][0]); o[3][1] = fmaf(p3, v4.y, o[3][1]);
            o[3][2] = fmaf(p3, v4.z, o[3][2]); o[3][3] = fmaf(p3, v4.w, o[3][3]);
        }
    }

    // Normalize and write y (B,T,C)
#pragma unroll
    for (int i = 0; i < 4; i++) {
        float inv = 1.0f / lrow[i];
        float4 v = {o[i][0] * inv, o[i][1] * inv, o[i][2] * inv, o[i][3] * inv};
        size_t idx = ((size_t)bb * Tt + q0 + r0 + i) * Cc + hh * 64 + c0;
        *reinterpret_cast<float4*>(&g_y[idx]) = v;
    }
}

// ---------------------------------------------------------------------------
extern "C" void kernel_launch(void* const* d_in, const int* in_sizes, int n_in,
                              void* d_out, int out_size)
{
    (void)in_sizes; (void)n_in; (void)out_size;
    const float* x      = (const float*)d_in[0];
    const int*   pad    = (const int*)d_in[1];
    const float* w_attn = (const float*)d_in[2];
    const float* w_proj = (const float*)d_in[3];
    const float* b_proj = (const float*)d_in[4];
    float* out = (float*)d_out;

    // QKV projection: (8192 x 1024) @ (1024 x 3072), scatter to q/k/v heads
    dim3 gq(3072 / 128, BT / 128);
    sa_gemm128<0><<<gq, 256>>>(x, w_attn, nullptr, nullptr, 3072);

    // Causal attention: 32 q-tiles x 64 (b,h)
    dim3 ga(Tt / 64, Bb * Hh);
    sa_attn64<<<ga, 256>>>(pad);

    // Output projection + bias
    dim3 gp(1024 / 128, BT / 128);
    sa_gemm128<1><<<gp, 256>>>(nullptr, w_proj, b_proj, out, 1024);
}

// round 2
// speedup vs baseline: 1.0452x; 1.0452x over previous
#include <cuda_runtime.h>
#include <cstdint>

typedef unsigned long long u64;

// Packed fp32x2 ops (Blackwell sm_10x; ptxas never auto-fuses these)
#define FMA2(d, a, b, c) \
    asm("fma.rn.f32x2 %0, %1, %2, %3;" : "=l"(d) : "l"(a), "l"(b), "l"(c))
#define MUL2(d, a, b) \
    asm("mul.rn.f32x2 %0, %1, %2;" : "=l"(d) : "l"(a), "l"(b))
#define PACK2(d, lo, hi) \
    asm("mov.b64 %0, {%1, %2};" : "=l"(d) : "f"(lo), "f"(hi))
#define UNPACK2(lo, hi, s) \
    asm("mov.b64 {%0, %1}, %2;" : "=f"(lo), "=f"(hi) : "l"(s))

// Problem constants
constexpr int Bb = 4;
constexpr int Tt = 2048;
constexpr int Cc = 1024;
constexpr int Hh = 16;
constexpr int HD = 64;
constexpr int BT = Bb * Tt;

// Scratch (device globals: the allowed allocation-free scratch path)
__device__ float g_q[(size_t)Bb * Hh * Tt * HD];   // (B,H,T,HD), pre-scaled by 1/8
__device__ float g_k[(size_t)Bb * Hh * Tt * HD];
__device__ float g_v[(size_t)Bb * Hh * Tt * HD];
__device__ float g_y[(size_t)Bb * Tt * Cc];        // attention output (B,T,C)

// ---------------------------------------------------------------------------
// Tiled GEMM: 128x128 tile, BK=16, 256 threads, 8x8 per thread, FFMA2 inner.
// Accumulators packed over j: acc2[i][jp] holds cols (2jp, 2jp+1) of row i.
// ---------------------------------------------------------------------------
template <int MODE>
__global__ __launch_bounds__(256, 2) void sa_gemm128(
    const float* __restrict__ Ain, const float* __restrict__ W,
    const float* __restrict__ bias, float* __restrict__ out, int N)
{
    constexpr int K = 1024;
    __shared__ float As[16][132];   // A tile transposed [k][m], padded
    __shared__ float Bs[16][128];   // B tile [k][n]

    const float* A = (MODE == 0) ? Ain : (const float*)g_y;
    int tid = threadIdx.x;
    int m0 = blockIdx.y * 128;
    int n0 = blockIdx.x * 128;
    int tm = tid >> 4;
    int tn = tid & 15;

    u64 acc2[8][4];
#pragma unroll
    for (int i = 0; i < 8; i++)
#pragma unroll
        for (int j = 0; j < 4; j++) acc2[i][j] = 0ull;

    for (int k0 = 0; k0 < K; k0 += 16) {
#pragma unroll
        for (int it = 0; it < 2; it++) {
            int f = tid + it * 256;           // 512 float4s
            int row = f >> 2, cg = f & 3;
            float4 v = *reinterpret_cast<const float4*>(
                A + (size_t)(m0 + row) * K + k0 + cg * 4);
            As[cg * 4 + 0][row] = v.x;
            As[cg * 4 + 1][row] = v.y;
            As[cg * 4 + 2][row] = v.z;
            As[cg * 4 + 3][row] = v.w;
        }
#pragma unroll
        for (int it = 0; it < 2; it++) {
            int f = tid + it * 256;
            int row = f >> 5, cg = f & 31;
            *reinterpret_cast<float4*>(&Bs[row][cg * 4]) =
                *reinterpret_cast<const float4*>(
                    W + (size_t)(k0 + row) * N + n0 + cg * 4);
        }
        __syncthreads();

#pragma unroll
        for (int kk = 0; kk < 16; kk++) {
            float a[8];
            *reinterpret_cast<float4*>(a)     = *reinterpret_cast<float4*>(&As[kk][tm * 8]);
            *reinterpret_cast<float4*>(a + 4) = *reinterpret_cast<float4*>(&As[kk][tm * 8 + 4]);
            // B pairs: contiguous 64-bit smem loads (no repack needed)
            ulonglong2 t0 = *reinterpret_cast<ulonglong2*>(&Bs[kk][tn * 8]);
            ulonglong2 t1 = *reinterpret_cast<ulonglong2*>(&Bs[kk][tn * 8 + 4]);
            u64 b2[4] = {t0.x, t0.y, t1.x, t1.y};
#pragma unroll
            for (int i = 0; i < 8; i++) {
                u64 ad;
                PACK2(ad, a[i], a[i]);
                FMA2(acc2[i][0], ad, b2[0], acc2[i][0]);
                FMA2(acc2[i][1], ad, b2[1], acc2[i][1]);
                FMA2(acc2[i][2], ad, b2[2], acc2[i][2]);
                FMA2(acc2[i][3], ad, b2[3], acc2[i][3]);
            }
        }
        __syncthreads();
    }

    // Unpack to scalar grid for the epilogue
    float acc[8][8];
#pragma unroll
    for (int i = 0; i < 8; i++)
#pragma unroll
        for (int jp = 0; jp < 4; jp++)
            UNPACK2(acc[i][2 * jp], acc[i][2 * jp + 1], acc2[i][jp]);

    if (MODE == 0) {
        // Scatter into q/k/v with layout (B,H,T,HD); q gets 1/sqrt(64) = 0.125
#pragma unroll
        for (int i = 0; i < 8; i++) {
            int m = m0 + tm * 8 + i;
            int bidx = m >> 11;
            int t = m & 2047;
#pragma unroll
            for (int jg = 0; jg < 2; jg++) {
                int n = n0 + tn * 8 + jg * 4;
                int part = n >> 10;        // 0=q 1=k 2=v
                int c = n & 1023;
                int h = c >> 6;
                int d = c & 63;
                float* dst = (part == 0) ? g_q : (part == 1) ? g_k : g_v;
                float sc = (part == 0) ? 0.125f : 1.0f;
                float4 v;
                v.x = acc[i][jg * 4 + 0] * sc;
                v.y = acc[i][jg * 4 + 1] * sc;
                v.z = acc[i][jg * 4 + 2] * sc;
                v.w = acc[i][jg * 4 + 3] * sc;
                size_t idx = ((((size_t)bidx * Hh + h) * Tt + t) * HD + d);
                *reinterpret_cast<float4*>(dst + idx) = v;
            }
        }
    } else {
#pragma unroll
        for (int i = 0; i < 8; i++) {
            int m = m0 + tm * 8 + i;
#pragma unroll
            for (int jg = 0; jg < 2; jg++) {
                int n = n0 + tn * 8 + jg * 4;
                float4 bv = *reinterpret_cast<const float4*>(bias + n);
                float4 v;
                v.x = acc[i][jg * 4 + 0] + bv.x;
                v.y = acc[i][jg * 4 + 1] + bv.y;
                v.z = acc[i][jg * 4 + 2] + bv.z;
                v.w = acc[i][jg * 4 + 3] + bv.w;
                *reinterpret_cast<float4*>(out + (size_t)m * N + n) = v;
            }
        }
    }
}

// ---------------------------------------------------------------------------
// Flash attention, 64x64 tiles, 256 threads, 4x4 per thread, FFMA2 inner.
// S = Q*K^T packs over the d (reduction) dim -> pure 2x, no duplication.
// O += P*V packs over j (V pairs contiguous, P duplicated).
// ---------------------------------------------------------------------------
__global__ __launch_bounds__(256, 2) void sa_attn64(const int* __restrict__ pad)
{
    __shared__ float Qs[64 * 64];
    __shared__ float KPs[64 * 64];   // K tile (swizzled), later reused as P [r][c]
    __shared__ float Vs[64 * 64];

    int tid = threadIdx.x;
    int qt = (int)gridDim.x - 1 - (int)blockIdx.x;   // big tiles first
    int bh = blockIdx.y;
    int bb = bh >> 4;
    int hh = bh & 15;
    int q0 = qt * 64;

    size_t base = (size_t)bh * Tt * HD;
    const float* Qg = g_q + base;
    const float* Kg = g_k + base;
    const float* Vg = g_v + base;

    int r0 = (tid >> 4) * 4;
    int c0 = (tid & 15) * 4;

#pragma unroll
    for (int it = 0; it < 4; it++) {
        int f = tid + it * 256;
        int row = f >> 4, dq = f & 15;
        *reinterpret_cast<float4*>(&Qs[row * 64 + dq * 4]) =
            *reinterpret_cast<const float4*>(Qg + (size_t)(q0 + row) * 64 + dq * 4);
    }

    u64 o2[4][2];   // output packed over j: (c0+0,c0+1), (c0+2,c0+3)
#pragma unroll
    for (int i = 0; i < 4; i++) { o2[i][0] = 0ull; o2[i][1] = 0ull; }
    float mrow[4] = {-1e30f, -1e30f, -1e30f, -1e30f};
    float lrow[4] = {0.0f, 0.0f, 0.0f, 0.0f};

    for (int kt = 0; kt <= qt; kt++) {
        __syncthreads();
        int k0 = kt * 64;
#pragma unroll
        for (int it = 0; it < 4; it++) {
            int f = tid + it * 256;
            int row = f >> 4, dq = f & 15;
            float4 kv = *reinterpret_cast<const float4*>(Kg + (size_t)(k0 + row) * 64 + dq * 4);
            float4 vv = *reinterpret_cast<const float4*>(Vg + (size_t)(k0 + row) * 64 + dq * 4);
            int dqs = dq ^ ((row >> 2) & 7);
            *reinterpret_cast<float4*>(&KPs[row * 64 + dqs * 4]) = kv;
            *reinterpret_cast<float4*>(&Vs[row * 64 + dq * 4]) = vv;
        }
        __syncthreads();

        // S = Q * K^T, packed over d (both operands contiguous pairs)
        u64 s2[4][4];
#pragma unroll
        for (int i = 0; i < 4; i++)
#pragma unroll
            for (int j = 0; j < 4; j++) s2[i][j] = 0ull;

        int sw = (c0 >> 2) & 7;
#pragma unroll
        for (int dq = 0; dq < 16; dq++) {
            ulonglong2 q2[4], k2[4];
#pragma unroll
            for (int i = 0; i < 4; i++)
                q2[i] = *reinterpret_cast<ulonglong2*>(&Qs[(r0 + i) * 64 + dq * 4]);
            int dqs = (dq ^ sw) * 4;
#pragma unroll
            for (int j = 0; j < 4; j++)
                k2[j] = *reinterpret_cast<ulonglong2*>(&KPs[(c0 + j) * 64 + dqs]);
#pragma unroll
            for (int i = 0; i < 4; i++)
#pragma unroll
                for (int j = 0; j < 4; j++) {
                    FMA2(s2[i][j], q2[i].x, k2[j].x, s2[i][j]);
                    FMA2(s2[i][j], q2[i].y, k2[j].y, s2[i][j]);
                }
        }

        // Reduce packed halves -> scalar scores
        float acc[4][4];
#pragma unroll
        for (int i = 0; i < 4; i++)
#pragma unroll
            for (int j = 0; j < 4; j++) {
                float lo, hi;
                UNPACK2(lo, hi, s2[i][j]);
                acc[i][j] = lo + hi;
            }

        // Mask: pad always; causal only on the diagonal tile
        bool diag = (kt == qt);
#pragma unroll
        for (int j = 0; j < 4; j++) {
            int pv = __ldg(&pad[bb * Tt + k0 + c0 + j]);
#pragma unroll
            for (int i = 0; i < 4; i++) {
                bool keep = (pv != 0) && (!diag || (r0 + i >= c0 + j));
                if (!keep) acc[i][j] = -1e30f;
            }
        }

        // Online softmax update (16-lane shuffle reductions per row)
#pragma unroll
        for (int i = 0; i < 4; i++) {
            float mt = fmaxf(fmaxf(acc[i][0], acc[i][1]), fmaxf(acc[i][2], acc[i][3]));
#pragma unroll
            for (int s = 1; s < 16; s <<= 1)
                mt = fmaxf(mt, __shfl_xor_sync(0xffffffffu, mt, s));
            float mnew = fmaxf(mrow[i], mt);
            float alpha = __expf(mrow[i] - mnew);
            float rs = 0.0f;
#pragma unroll
            for (int j = 0; j < 4; j++) {
                acc[i][j] = __expf(acc[i][j] - mnew);
                rs += acc[i][j];
            }
#pragma unroll
            for (int s = 1; s < 16; s <<= 1)
                rs += __shfl_xor_sync(0xffffffffu, rs, s);
            lrow[i] = lrow[i] * alpha + rs;
            mrow[i] = mnew;
            u64 al2;
            PACK2(al2, alpha, alpha);
            MUL2(o2[i][0], o2[i][0], al2);
            MUL2(o2[i][1], o2[i][1], al2);
        }

        __syncthreads();

        // Write P [r][c] into KPs
#pragma unroll
        for (int i = 0; i < 4; i++) {
            float4 pv4 = {acc[i][0], acc[i][1], acc[i][2], acc[i][3]};
            *reinterpret_cast<float4*>(&KPs[(r0 + i) * 64 + c0]) = pv4;
        }
        __syncthreads();

        // O += P * V, packed over j (V pairs contiguous)
#pragma unroll 8
        for (int jj = 0; jj < 64; jj++) {
            ulonglong2 v2 = *reinterpret_cast<ulonglong2*>(&Vs[jj * 64 + c0]);
            float p0 = KPs[(r0 + 0) * 64 + jj];
            float p1 = KPs[(r0 + 1) * 64 + jj];
            float p2 = KPs[(r0 + 2) * 64 + jj];
            float p3 = KPs[(r0 + 3) * 64 + jj];
            u64 pd;
            PACK2(pd, p0, p0);
            FMA2(o2[0][0], pd, v2.x, o2[0][0]); FMA2(o2[0][1], pd, v2.y, o2[0][1]);
            PACK2(pd, p1, p1);
            FMA2(o2[1][0], pd, v2.x, o2[1][0]); FMA2(o2[1][1], pd, v2.y, o2[1][1]);
            PACK2(pd, p2, p2);
            FMA2(o2[2][0], pd, v2.x, o2[2][0]); FMA2(o2[2][1], pd, v2.y, o2[2][1]);
            PACK2(pd, p3, p3);
            FMA2(o2[3][0], pd, v2.x, o2[3][0]); FMA2(o2[3][1], pd, v2.y, o2[3][1]);
        }
    }

    // Normalize and write y (B,T,C)
#pragma unroll
    for (int i = 0; i < 4; i++) {
        float inv = 1.0f / lrow[i];
        float o00, o01, o10, o11;
        UNPACK2(o00, o01, o2[i][0]);
        UNPACK2(o10, o11, o2[i][1]);
        float4 v = {o00 * inv, o01 * inv, o10 * inv, o11 * inv};
        size_t idx = ((size_t)bb * Tt + q0 + r0 + i) * Cc + hh * 64 + c0;
        *reinterpret_cast<float4*>(&g_y[idx]) = v;
    }
}

// ---------------------------------------------------------------------------
extern "C" void kernel_launch(void* const* d_in, const int* in_sizes, int n_in,
                              void* d_out, int out_size)
{
    (void)in_sizes; (void)n_in; (void)out_size;
    const float* x      = (const float*)d_in[0];
    const int*   pad    = (const int*)d_in[1];
    const float* w_attn = (const float*)d_in[2];
    const float* w_proj = (const float*)d_in[3];
    const float* b_proj = (const float*)d_in[4];
    float* out = (float*)d_out;

    dim3 gq(3072 / 128, BT / 128);
    sa_gemm128<0><<<gq, 256>>>(x, w_attn, nullptr, nullptr, 3072);

    dim3 ga(Tt / 64, Bb * Hh);
    sa_attn64<<<ga, 256>>>(pad);

    dim3 gp(1024 / 128, BT / 128);
    sa_gemm128<1><<<gp, 256>>>(nullptr, w_proj, b_proj, out, 1024);
}

// round 4
// speedup vs baseline: 1.6176x; 1.5476x over previous
#include <cuda_runtime.h>
#include <cuda_bf16.h>
#include <cstdint>

typedef unsigned long long u64;

// ---------------- packed fp32x2 (attention kernel) ----------------
#define FMA2(d, a, b, c) \
    asm("fma.rn.f32x2 %0, %1, %2, %3;" : "=l"(d) : "l"(a), "l"(b), "l"(c))
#define MUL2(d, a, b) \
    asm("mul.rn.f32x2 %0, %1, %2;" : "=l"(d) : "l"(a), "l"(b))
#define PACK2(d, lo, hi) \
    asm("mov.b64 %0, {%1, %2};" : "=l"(d) : "f"(lo), "f"(hi))
#define UNPACK2(lo, hi, s) \
    asm("mov.b64 {%0, %1}, %2;" : "=f"(lo), "=f"(hi) : "l"(s))

__device__ __forceinline__ uint32_t smem_u32(const void* p) {
    uint32_t a;
    asm("{ .reg .u64 t; cvta.to.shared.u64 t, %1; cvt.u32.u64 %0, t; }" : "=r"(a) : "l"(p));
    return a;
}
__device__ __forceinline__ void ldsm4(uint32_t* r, uint32_t addr) {
    asm volatile("ldmatrix.sync.aligned.m8n8.x4.shared.b16 {%0,%1,%2,%3}, [%4];"
                 : "=r"(r[0]), "=r"(r[1]), "=r"(r[2]), "=r"(r[3]) : "r"(addr));
}
__device__ __forceinline__ void mma16816(float* d, const uint32_t* a, const uint32_t* b) {
    asm volatile(
        "mma.sync.aligned.m16n8k16.row.col.f32.bf16.bf16.f32 "
        "{%0,%1,%2,%3}, {%4,%5,%6,%7}, {%8,%9}, {%0,%1,%2,%3};"
        : "+f"(d[0]), "+f"(d[1]), "+f"(d[2]), "+f"(d[3])
        : "r"(a[0]), "r"(a[1]), "r"(a[2]), "r"(a[3]), "r"(b[0]), "r"(b[1]));
}
__device__ __forceinline__ void cpasync16(uint32_t dst, const void* src) {
    asm volatile("cp.async.cg.shared.global [%0], [%1], 16;" :: "r"(dst), "l"(src));
}
#define CP_COMMIT() asm volatile("cp.async.commit_group;" ::: "memory")
#define CP_WAIT1()  asm volatile("cp.async.wait_group 1;" ::: "memory")

// ---------------- problem constants ----------------
constexpr int Bb = 4, Tt = 2048, Cc = 1024, Hh = 16, HD = 64;
constexpr int BT = Bb * Tt;           // 8192
constexpr int Kd = 1024;
constexpr int STAGE = 65536;          // 4 tiles x 16KB per pipeline stage
constexpr int GSM_BYTES = 2 * STAGE;  // 128 KB

// ---------------- scratch (device globals) ----------------
__device__ float g_q[(size_t)Bb * Hh * Tt * HD];
__device__ float g_k[(size_t)Bb * Hh * Tt * HD];
__device__ float g_v[(size_t)Bb * Hh * Tt * HD];
__device__ float g_y[(size_t)Bb * Tt * Cc];
__device__ __nv_bfloat16 gx_h[(size_t)BT * Kd],  gx_l[(size_t)BT * Kd];
__device__ __nv_bfloat16 gy_h[(size_t)BT * Kd],  gy_l[(size_t)BT * Kd];
__device__ __nv_bfloat16 gwa_h[(size_t)3072 * Kd], gwa_l[(size_t)3072 * Kd];  // w_attn^T
__device__ __nv_bfloat16 gwp_h[(size_t)1024 * Kd], gwp_l[(size_t)1024 * Kd];  // w_proj^T

// ---------------- conversion kernels ----------------
__global__ void k_split(const float4* __restrict__ src, __nv_bfloat162* __restrict__ h,
                        __nv_bfloat162* __restrict__ l, int n4)
{
    int i = blockIdx.x * blockDim.x + threadIdx.x;
    if (i >= n4) return;
    float4 v = src[i];
    __nv_bfloat16 h0 = __float2bfloat16(v.x), h1 = __float2bfloat16(v.y);
    __nv_bfloat16 h2 = __float2bfloat16(v.z), h3 = __float2bfloat16(v.w);
    h[i * 2]     = __halves2bfloat162(h0, h1);
    h[i * 2 + 1] = __halves2bfloat162(h2, h3);
    l[i * 2]     = __halves2bfloat162(__float2bfloat16(v.x - __bfloat162float(h0)),
                                      __float2bfloat16(v.y - __bfloat162float(h1)));
    l[i * 2 + 1] = __halves2bfloat162(__float2bfloat16(v.z - __bfloat162float(h2)),
                                      __float2bfloat16(v.w - __bfloat162float(h3)));
}

// transpose + split: src[1024][Ncols] fp32 -> out[Ncols][1024] bf16 hi/lo
__global__ void k_splitT(const float* __restrict__ src, __nv_bfloat16* __restrict__ h,
                         __nv_bfloat16* __restrict__ l, int Ncols)
{
    __shared__ float ts[32][33];
    int tx = threadIdx.x, ty = threadIdx.y;
    int c0 = blockIdx.x * 32, r0 = blockIdx.y * 32;
#pragma unroll
    for (int i = 0; i < 4; i++)
        ts[ty + i * 8][tx] = src[(size_t)(r0 + ty + i * 8) * Ncols + c0 + tx];
    __syncthreads();
#pragma unroll
    for (int i = 0; i < 4; i++) {
        int n = c0 + ty + i * 8, k = r0 + tx;
        float v = ts[tx][ty + i * 8];
        __nv_bfloat16 hv = __float2bfloat16(v);
        h[(size_t)n * 1024 + k] = hv;
        l[(size_t)n * 1024 + k] = __float2bfloat16(v - __bfloat162float(hv));
    }
}

// ---------------------------------------------------------------------------
// mma.sync bf16-split GEMM: D[128x128 fp32] = Ah*Bh^T + Ah*Bl^T + Al*Bh^T
// A[m][k], B[n][k] K-major bf16 (K=1024). BK=64, cp.async double-buffered.
// 8 warps in 2x4 grid; each warp 64x32 via 4x4 grid of m16n8k16 tiles.
// MODE 0: scatter to g_q/g_k/g_v (q scaled 0.125). MODE 1: out + bias.
// ---------------------------------------------------------------------------
template <int MODE>
__global__ __launch_bounds__(256, 1) void sa_gemm_mma(
    const __nv_bfloat16* __restrict__ Ah, const __nv_bfloat16* __restrict__ Al,
    const __nv_bfloat16* __restrict__ Bh, const __nv_bfloat16* __restrict__ Bl,
    const float* __restrict__ bias, float* __restrict__ out, int N)
{
    extern __shared__ char smem[];
    uint32_t sb = smem_u32(smem);
    int tid = threadIdx.x, lane = tid & 31, warp = tid >> 5;
    int m0 = blockIdx.y * 128, n0 = blockIdx.x * 128;
    int wm = (warp >> 2) * 64, wn = (warp & 3) * 32;

    const __nv_bfloat16* srcs[4] = {Ah, Al, Bh, Bl};

    auto load_stage = [&](int st, int c) {
        uint32_t sbase = sb + st * STAGE;
        int kc0 = c * 64;
#pragma unroll
        for (int tile = 0; tile < 4; tile++) {
            int base0 = (tile < 2) ? m0 : n0;
            const __nv_bfloat16* src = srcs[tile] + (size_t)base0 * Kd + kc0;
#pragma unroll
            for (int i = 0; i < 4; i++) {
                int id = tid + i * 256;           // 1024 16B chunks per tile
                int row = id >> 3, cch = id & 7;
                cpasync16(sbase + tile * 16384 + row * 128 + ((cch ^ (row & 7)) << 4),
                          src + (size_t)row * Kd + cch * 8);
            }
        }
    };

    float acc[4][4][4];
#pragma unroll
    for (int a = 0; a < 4; a++)
#pragma unroll
        for (int b = 0; b < 4; b++)
#pragma unroll
            for (int e = 0; e < 4; e++) acc[a][b][e] = 0.0f;

    load_stage(0, 0);
    CP_COMMIT();

    for (int c = 0; c < 16; c++) {
        if (c + 1 < 16) load_stage((c + 1) & 1, c + 1);
        CP_COMMIT();
        CP_WAIT1();
        __syncthreads();
        uint32_t sbase = sb + (c & 1) * STAGE;
#pragma unroll
        for (int ks = 0; ks < 4; ks++) {
            uint32_t ah[4][4], al[4][4], bh[4][2], bl[4][2];
#pragma unroll
            for (int mt = 0; mt < 4; mt++) {
                int row = wm + mt * 16 + (lane & 15);
                int cch = ks * 2 + (lane >> 4);
                uint32_t off = row * 128 + ((cch ^ (row & 7)) << 4);
                ldsm4(ah[mt], sbase + off);             // Ah tile at +0
                ldsm4(al[mt], sbase + 16384 + off);     // Al tile
            }
#pragma unroll
            for (int nt = 0; nt < 2; nt++) {
                int row = wn + nt * 16 + (lane & 15);
                int cch = ks * 2 + (lane >> 4);
                uint32_t off = row * 128 + ((cch ^ (row & 7)) << 4);
                uint32_t t[4];
                ldsm4(t, sbase + 32768 + off);          // Bh
                bh[nt * 2][0] = t[0]; bh[nt * 2][1] = t[2];
                bh[nt * 2 + 1][0] = t[1]; bh[nt * 2 + 1][1] = t[3];
                ldsm4(t, sbase + 49152 + off);          // Bl
                bl[nt * 2][0] = t[0]; bl[nt * 2][1] = t[2];
                bl[nt * 2 + 1][0] = t[1]; bl[nt * 2 + 1][1] = t[3];
            }
#pragma unroll
            for (int mt = 0; mt < 4; mt++)
#pragma unroll
                for (int j = 0; j < 4; j++) {
                    mma16816(acc[mt][j], ah[mt], bh[j]);
                    mma16816(acc[mt][j], ah[mt], bl[j]);
                    mma16816(acc[mt][j], al[mt], bh[j]);
                }
        }
        __syncthreads();
    }

    // Epilogue: fragment layout d0,d1=row gr cols 2c,2c+1; d2,d3=row gr+8
#pragma unroll
    for (int mt = 0; mt < 4; mt++)
#pragma unroll
        for (int j = 0; j < 4; j++) {
            int n = n0 + wn + j * 8 + (lane & 3) * 2;
            int mA = m0 + wm + mt * 16 + (lane >> 2);
#pragma unroll
            for (int half = 0; half < 2; half++) {
                int m = mA + half * 8;
                float2 v = {acc[mt][j][half * 2], acc[mt][j][half * 2 + 1]};
                if (MODE == 0) {
                    int part = n >> 10, c1 = n & 1023, h = c1 >> 6, dd = c1 & 63;
                    float* dst = (part == 0) ? g_q : (part == 1) ? g_k : g_v;
                    if (part == 0) { v.x *= 0.125f; v.y *= 0.125f; }
                    int bidx = m >> 11, t = m & 2047;
                    *reinterpret_cast<float2*>(
                        dst + ((((size_t)bidx * Hh + h) * Tt + t) * HD + dd)) = v;
                } else {
                    v.x += __ldg(bias + n);
                    v.y += __ldg(bias + n + 1);
                    *reinterpret_cast<float2*>(out + (size_t)m * N + n) = v;
                }
            }
        }
}

// ---------------------------------------------------------------------------
// Flash attention (unchanged): 64x64 tiles, FFMA2 inner loops
// ---------------------------------------------------------------------------
__global__ __launch_bounds__(256, 2) void sa_attn64(const int* __restrict__ pad)
{
    __shared__ float Qs[64 * 64];
    __shared__ float KPs[64 * 64];
    __shared__ float Vs[64 * 64];

    int tid = threadIdx.x;
    int qt = (int)gridDim.x - 1 - (int)blockIdx.x;
    int bh = blockIdx.y;
    int bb = bh >> 4;
    int hh = bh & 15;
    int q0 = qt * 64;

    size_t base = (size_t)bh * Tt * HD;
    const float* Qg = g_q + base;
    const float* Kg = g_k + base;
    const float* Vg = g_v + base;

    int r0 = (tid >> 4) * 4;
    int c0 = (tid & 15) * 4;

#pragma unroll
    for (int it = 0; it < 4; it++) {
        int f = tid + it * 256;
        int row = f >> 4, dq = f & 15;
        *reinterpret_cast<float4*>(&Qs[row * 64 + dq * 4]) =
            *reinterpret_cast<const float4*>(Qg + (size_t)(q0 + row) * 64 + dq * 4);
    }

    u64 o2[4][2];
#pragma unroll
    for (int i = 0; i < 4; i++) { o2[i][0] = 0ull; o2[i][1] = 0ull; }
    float mrow[4] = {-1e30f, -1e30f, -1e30f, -1e30f};
    float lrow[4] = {0.0f, 0.0f, 0.0f, 0.0f};

    for (int kt = 0; kt <= qt; kt++) {
        __syncthreads();
        int k0 = kt * 64;
#pragma unroll
        for (int it = 0; it < 4; it++) {
            int f = tid + it * 256;
            int row = f >> 4, dq = f & 15;
            float4 kv = *reinterpret_cast<const float4*>(Kg + (size_t)(k0 + row) * 64 + dq * 4);
            float4 vv = *reinterpret_cast<const float4*>(Vg + (size_t)(k0 + row) * 64 + dq * 4);
            int dqs = dq ^ ((row >> 2) & 7);
            *reinterpret_cast<float4*>(&KPs[row * 64 + dqs * 4]) = kv;
            *reinterpret_cast<float4*>(&Vs[row * 64 + dq * 4]) = vv;
        }
        __syncthreads();

        u64 s2[4][4];
#pragma unroll
        for (int i = 0; i < 4; i++)
#pragma unroll
            for (int j = 0; j < 4; j++) s2[i][j] = 0ull;

        int sw = (c0 >> 2) & 7;
#pragma unroll
        for (int dq = 0; dq < 16; dq++) {
            ulonglong2 q2[4], k2[4];
#pragma unroll
            for (int i = 0; i < 4; i++)
                q2[i] = *reinterpret_cast<ulonglong2*>(&Qs[(r0 + i) * 64 + dq * 4]);
            int dqs = (dq ^ sw) * 4;
#pragma unroll
            for (int j = 0; j < 4; j++)
                k2[j] = *reinterpret_cast<ulonglong2*>(&KPs[(c0 + j) * 64 + dqs]);
#pragma unroll
            for (int i = 0; i < 4; i++)
#pragma unroll
                for (int j = 0; j < 4; j++) {
                    FMA2(s2[i][j], q2[i].x, k2[j].x, s2[i][j]);
                    FMA2(s2[i][j], q2[i].y, k2[j].y, s2[i][j]);
                }
        }

        float acc[4][4];
#pragma unroll
        for (int i = 0; i < 4; i++)
#pragma unroll
            for (int j = 0; j < 4; j++) {
                float lo, hi;
                UNPACK2(lo, hi, s2[i][j]);
                acc[i][j] = lo + hi;
            }

        bool diag = (kt == qt);
#pragma unroll
        for (int j = 0; j < 4; j++) {
            int pv = __ldg(&pad[bb * Tt + k0 + c0 + j]);
#pragma unroll
            for (int i = 0; i < 4; i++) {
                bool keep = (pv != 0) && (!diag || (r0 + i >= c0 + j));
                if (!keep) acc[i][j] = -1e30f;
            }
        }

#pragma unroll
        for (int i = 0; i < 4; i++) {
            float mt = fmaxf(fmaxf(acc[i][0], acc[i][1]), fmaxf(acc[i][2], acc[i][3]));
#pragma unroll
            for (int s = 1; s < 16; s <<= 1)
                mt = fmaxf(mt, __shfl_xor_sync(0xffffffffu, mt, s));
            float mnew = fmaxf(mrow[i], mt);
            float alpha = __expf(mrow[i] - mnew);
            float rs = 0.0f;
#pragma unroll
            for (int j = 0; j < 4; j++) {
                acc[i][j] = __expf(acc[i][j] - mnew);
                rs += acc[i][j];
            }
#pragma unroll
            for (int s = 1; s < 16; s <<= 1)
                rs += __shfl_xor_sync(0xffffffffu, rs, s);
            lrow[i] = lrow[i] * alpha + rs;
            mrow[i] = mnew;
            u64 al2;
            PACK2(al2, alpha, alpha);
            MUL2(o2[i][0], o2[i][0], al2);
            MUL2(o2[i][1], o2[i][1], al2);
        }

        __syncthreads();
#pragma unroll
        for (int i = 0; i < 4; i++) {
            float4 pv4 = {acc[i][0], acc[i][1], acc[i][2], acc[i][3]};
            *reinterpret_cast<float4*>(&KPs[(r0 + i) * 64 + c0]) = pv4;
        }
        __syncthreads();

#pragma unroll 8
        for (int jj = 0; jj < 64; jj++) {
            ulonglong2 v2 = *reinterpret_cast<ulonglong2*>(&Vs[jj * 64 + c0]);
            float p0 = KPs[(r0 + 0) * 64 + jj];
            float p1 = KPs[(r0 + 1) * 64 + jj];
            float p2 = KPs[(r0 + 2) * 64 + jj];
            float p3 = KPs[(r0 + 3) * 64 + jj];
            u64 pd;
            PACK2(pd, p0, p0);
            FMA2(o2[0][0], pd, v2.x, o2[0][0]); FMA2(o2[0][1], pd, v2.y, o2[0][1]);
            PACK2(pd, p1, p1);
            FMA2(o2[1][0], pd, v2.x, o2[1][0]); FMA2(o2[1][1], pd, v2.y, o2[1][1]);
            PACK2(pd, p2, p2);
            FMA2(o2[2][0], pd, v2.x, o2[2][0]); FMA2(o2[2][1], pd, v2.y, o2[2][1]);
            PACK2(pd, p3, p3);
            FMA2(o2[3][0], pd, v2.x, o2[3][0]); FMA2(o2[3][1], pd, v2.y, o2[3][1]);
        }
    }

#pragma unroll
    for (int i = 0; i < 4; i++) {
        float inv = 1.0f / lrow[i];
        float o00, o01, o10, o11;
        UNPACK2(o00, o01, o2[i][0]);
        UNPACK2(o10, o11, o2[i][1]);
        float4 v = {o00 * inv, o01 * inv, o10 * inv, o11 * inv};
        size_t idx = ((size_t)bb * Tt + q0 + r0 + i) * Cc + hh * 64 + c0;
        *reinterpret_cast<float4*>(&g_y[idx]) = v;
    }
}

// ---------------------------------------------------------------------------
extern "C" void kernel_launch(void* const* d_in, const int* in_sizes, int n_in,
                              void* d_out, int out_size)
{
    (void)in_sizes; (void)n_in; (void)out_size;
    const float* x      = (const float*)d_in[0];
    const int*   pad    = (const int*)d_in[1];
    const float* w_attn = (const float*)d_in[2];
    const float* w_proj = (const float*)d_in[3];
    const float* b_proj = (const float*)d_in[4];
    float* out = (float*)d_out;

    cudaFuncSetAttribute(sa_gemm_mma<0>, cudaFuncAttributeMaxDynamicSharedMemorySize, GSM_BYTES);
    cudaFuncSetAttribute(sa_gemm_mma<1>, cudaFuncAttributeMaxDynamicSharedMemorySize, GSM_BYTES);

    void *pxh, *pxl, *pyh, *pyl, *pwah, *pwal, *pwph, *pwpl, *pgy;
    cudaGetSymbolAddress(&pxh, gx_h);  cudaGetSymbolAddress(&pxl, gx_l);
    cudaGetSymbolAddress(&pyh, gy_h);  cudaGetSymbolAddress(&pyl, gy_l);
    cudaGetSymbolAddress(&pwah, gwa_h); cudaGetSymbolAddress(&pwal, gwa_l);
    cudaGetSymbolAddress(&pwph, gwp_h); cudaGetSymbolAddress(&pwpl, gwp_l);
    cudaGetSymbolAddress(&pgy, g_y);

    // Split x; transpose+split weights
    k_split<<<(BT * Kd / 4 + 255) / 256, 256>>>(
        (const float4*)x, (__nv_bfloat162*)pxh, (__nv_bfloat162*)pxl, BT * Kd / 4);
    k_splitT<<<dim3(3072 / 32, Kd / 32), dim3(32, 8)>>>(
        w_attn, (__nv_bfloat16*)pwah, (__nv_bfloat16*)pwal, 3072);
    k_splitT<<<dim3(1024 / 32, Kd / 32), dim3(32, 8)>>>(
        w_proj, (__nv_bfloat16*)pwph, (__nv_bfloat16*)pwpl, 1024);

    // QKV projection on tensor cores (mma.sync)
    sa_gemm_mma<0><<<dim3(3072 / 128, BT / 128), 256, GSM_BYTES>>>(
        (const __nv_bfloat16*)pxh, (const __nv_bfloat16*)pxl,
        (const __nv_bfloat16*)pwah, (const __nv_bfloat16*)pwal,
        nullptr, nullptr, 3072);

    // Attention
    sa_attn64<<<dim3(Tt / 64, Bb * Hh), 256>>>(pad);

    // Split y, then output projection on tensor cores
    k_split<<<(BT * Kd / 4 + 255) / 256, 256>>>(
        (const float4*)pgy, (__nv_bfloat162*)pyh, (__nv_bfloat162*)pyl, BT * Kd / 4);
    sa_gemm_mma<1><<<dim3(1024 / 128, BT / 128), 256, GSM_BYTES>>>(
        (const __nv_bfloat16*)pyh, (const __nv_bfloat16*)pyl,
        (const __nv_bfloat16*)pwph, (const __nv_bfloat16*)pwpl,
        b_proj, out, 1024);
}

// round 6
// speedup vs baseline: 2.6944x; 1.6657x over previous
#include <cuda_runtime.h>
#include <cuda_bf16.h>
#include <cstdint>

typedef unsigned long long u64;

__device__ __forceinline__ uint32_t smem_u32(const void* p) {
    uint32_t a;
    asm("{ .reg .u64 t; cvta.to.shared.u64 t, %1; cvt.u32.u64 %0, t; }" : "=r"(a) : "l"(p));
    return a;
}
__device__ __forceinline__ void ldsm4(uint32_t* r, uint32_t addr) {
    asm volatile("ldmatrix.sync.aligned.m8n8.x4.shared.b16 {%0,%1,%2,%3}, [%4];"
                 : "=r"(r[0]), "=r"(r[1]), "=r"(r[2]), "=r"(r[3]) : "r"(addr));
}
__device__ __forceinline__ void mma16816(float* d, const uint32_t* a, const uint32_t* b) {
    asm volatile(
        "mma.sync.aligned.m16n8k16.row.col.f32.bf16.bf16.f32 "
        "{%0,%1,%2,%3}, {%4,%5,%6,%7}, {%8,%9}, {%0,%1,%2,%3};"
        : "+f"(d[0]), "+f"(d[1]), "+f"(d[2]), "+f"(d[3])
        : "r"(a[0]), "r"(a[1]), "r"(a[2]), "r"(a[3]), "r"(b[0]), "r"(b[1]));
}
__device__ __forceinline__ void cpasync16(uint32_t dst, const void* src) {
    asm volatile("cp.async.cg.shared.global [%0], [%1], 16;" :: "r"(dst), "l"(src));
}
#define CP_COMMIT() asm volatile("cp.async.commit_group;" ::: "memory")
#define CP_WAIT1()  asm volatile("cp.async.wait_group 1;" ::: "memory")
#define CP_WAIT0()  asm volatile("cp.async.wait_group 0;" ::: "memory")

// pack 2 floats -> bf16x2 (lo in low half)
__device__ __forceinline__ uint32_t packbf(float lo, float hi) {
    uint32_t d;
    asm("cvt.rn.bf16x2.f32 %0, %1, %2;" : "=r"(d) : "f"(hi), "f"(lo));
    return d;
}
// residual pack: lo/hi minus their bf16 hi-parts (bf16->f32 is a shift)
__device__ __forceinline__ uint32_t packlo(uint32_t hpk, float lo, float hi) {
    float h0 = __uint_as_float(hpk << 16);
    float h1 = __uint_as_float(hpk & 0xffff0000u);
    return packbf(lo - h0, hi - h1);
}

// ---------------- problem constants ----------------
constexpr int Bb = 4, Tt = 2048, Cc = 1024, Hh = 16, HD = 64;
constexpr int BT = Bb * Tt;
constexpr int Kd = 1024;
constexpr int STAGE = 65536;           // GEMM: 4 tiles x 16KB
constexpr int GSM_BYTES = 2 * STAGE;
constexpr int ASTAGE = 65536;          // attn: Kh,Kl,Vth,Vtl x 16KB
constexpr int ASM_BYTES = 2 * ASTAGE;

// ---------------- scratch (device globals) ----------------
constexpr size_t QKV = (size_t)Bb * Hh * Tt * HD;   // 8388608
__device__ __nv_bfloat16 g_qh[QKV], g_ql[QKV];      // [b,h,t,d], q pre-scaled 0.125
__device__ __nv_bfloat16 g_kh[QKV], g_kl[QKV];      // [b,h,t,d]
__device__ __nv_bfloat16 g_vth[QKV], g_vtl[QKV];    // [b,h,d,t]  (transposed V)
__device__ __nv_bfloat16 gx_h[(size_t)BT * Kd],  gx_l[(size_t)BT * Kd];
__device__ __nv_bfloat16 gy_h[(size_t)BT * Kd],  gy_l[(size_t)BT * Kd];
__device__ __nv_bfloat16 gwa_h[(size_t)3072 * Kd], gwa_l[(size_t)3072 * Kd];
__device__ __nv_bfloat16 gwp_h[(size_t)1024 * Kd], gwp_l[(size_t)1024 * Kd];

// ---------------- conversion kernels ----------------
__global__ void k_split(const float4* __restrict__ src, __nv_bfloat162* __restrict__ h,
                        __nv_bfloat162* __restrict__ l, int n4)
{
    int i = blockIdx.x * blockDim.x + threadIdx.x;
    if (i >= n4) return;
    float4 v = src[i];
    __nv_bfloat16 h0 = __float2bfloat16(v.x), h1 = __float2bfloat16(v.y);
    __nv_bfloat16 h2 = __float2bfloat16(v.z), h3 = __float2bfloat16(v.w);
    h[i * 2]     = __halves2bfloat162(h0, h1);
    h[i * 2 + 1] = __halves2bfloat162(h2, h3);
    l[i * 2]     = __halves2bfloat162(__float2bfloat16(v.x - __bfloat162float(h0)),
                                      __float2bfloat16(v.y - __bfloat162float(h1)));
    l[i * 2 + 1] = __halves2bfloat162(__float2bfloat16(v.z - __bfloat162float(h2)),
                                      __float2bfloat16(v.w - __bfloat162float(h3)));
}

__global__ void k_splitT(const float* __restrict__ src, __nv_bfloat16* __restrict__ h,
                         __nv_bfloat16* __restrict__ l, int Ncols)
{
    __shared__ float ts[32][33];
    int tx = threadIdx.x, ty = threadIdx.y;
    int c0 = blockIdx.x * 32, r0 = blockIdx.y * 32;
#pragma unroll
    for (int i = 0; i < 4; i++)
        ts[ty + i * 8][tx] = src[(size_t)(r0 + ty + i * 8) * Ncols + c0 + tx];
    __syncthreads();
#pragma unroll
    for (int i = 0; i < 4; i++) {
        int n = c0 + ty + i * 8, k = r0 + tx;
        float v = ts[tx][ty + i * 8];
        __nv_bfloat16 hv = __float2bfloat16(v);
        h[(size_t)n * 1024 + k] = hv;
        l[(size_t)n * 1024 + k] = __float2bfloat16(v - __bfloat162float(hv));
    }
}

// ---------------------------------------------------------------------------
// mma.sync bf16-split GEMM (round-4 verified core).
// MODE 0: epilogue writes q/k bf16 hi/lo [b,h,t,d] and V^T hi/lo [b,h,d,t].
// MODE 1: fp32 out + bias.
// ---------------------------------------------------------------------------
template <int MODE>
__global__ __launch_bounds__(256, 1) void sa_gemm_mma(
    const __nv_bfloat16* __restrict__ Ah, const __nv_bfloat16* __restrict__ Al,
    const __nv_bfloat16* __restrict__ Bh, const __nv_bfloat16* __restrict__ Bl,
    const float* __restrict__ bias, float* __restrict__ out, int N)
{
    extern __shared__ char smem[];
    uint32_t sb = smem_u32(smem);
    int tid = threadIdx.x, lane = tid & 31, warp = tid >> 5;
    int m0 = blockIdx.y * 128, n0 = blockIdx.x * 128;
    int wm = (warp >> 2) * 64, wn = (warp & 3) * 32;

    const __nv_bfloat16* srcs[4] = {Ah, Al, Bh, Bl};

    auto load_stage = [&](int st, int c) {
        uint32_t sbase = sb + st * STAGE;
        int kc0 = c * 64;
#pragma unroll
        for (int tile = 0; tile < 4; tile++) {
            int base0 = (tile < 2) ? m0 : n0;
            const __nv_bfloat16* src = srcs[tile] + (size_t)base0 * Kd + kc0;
#pragma unroll
            for (int i = 0; i < 4; i++) {
                int id = tid + i * 256;
                int row = id >> 3, cch = id & 7;
                cpasync16(sbase + tile * 16384 + row * 128 + ((cch ^ (row & 7)) << 4),
                          src + (size_t)row * Kd + cch * 8);
            }
        }
    };

    float acc[4][4][4];
#pragma unroll
    for (int a = 0; a < 4; a++)
#pragma unroll
        for (int b = 0; b < 4; b++)
#pragma unroll
            for (int e = 0; e < 4; e++) acc[a][b][e] = 0.0f;

    load_stage(0, 0);
    CP_COMMIT();

    for (int c = 0; c < 16; c++) {
        if (c + 1 < 16) load_stage((c + 1) & 1, c + 1);
        CP_COMMIT();
        CP_WAIT1();
        __syncthreads();
        uint32_t sbase = sb + (c & 1) * STAGE;
#pragma unroll
        for (int ks = 0; ks < 4; ks++) {
            uint32_t ah[4][4], al[4][4], bh[4][2], bl[4][2];
#pragma unroll
            for (int mt = 0; mt < 4; mt++) {
                int row = wm + mt * 16 + (lane & 15);
                int cch = ks * 2 + (lane >> 4);
                uint32_t off = row * 128 + ((cch ^ (row & 7)) << 4);
                ldsm4(ah[mt], sbase + off);
                ldsm4(al[mt], sbase + 16384 + off);
            }
#pragma unroll
            for (int nt = 0; nt < 2; nt++) {
                int row = wn + nt * 16 + (lane & 15);
                int cch = ks * 2 + (lane >> 4);
                uint32_t off = row * 128 + ((cch ^ (row & 7)) << 4);
                uint32_t t[4];
                ldsm4(t, sbase + 32768 + off);
                bh[nt * 2][0] = t[0]; bh[nt * 2][1] = t[2];
                bh[nt * 2 + 1][0] = t[1]; bh[nt * 2 + 1][1] = t[3];
                ldsm4(t, sbase + 49152 + off);
                bl[nt * 2][0] = t[0]; bl[nt * 2][1] = t[2];
                bl[nt * 2 + 1][0] = t[1]; bl[nt * 2 + 1][1] = t[3];
            }
#pragma unroll
            for (int mt = 0; mt < 4; mt++)
#pragma unroll
                for (int j = 0; j < 4; j++) {
                    mma16816(acc[mt][j], ah[mt], bh[j]);
                    mma16816(acc[mt][j], ah[mt], bl[j]);
                    mma16816(acc[mt][j], al[mt], bh[j]);
                }
        }
        __syncthreads();
    }

#pragma unroll
    for (int mt = 0; mt < 4; mt++)
#pragma unroll
        for (int j = 0; j < 4; j++) {
            int n = n0 + wn + j * 8 + (lane & 3) * 2;
            int mA = m0 + wm + mt * 16 + (lane >> 2);
#pragma unroll
            for (int half = 0; half < 2; half++) {
                int m = mA + half * 8;
                float f0 = acc[mt][j][half * 2], f1 = acc[mt][j][half * 2 + 1];
                if (MODE == 0) {
                    int part = n >> 10, c1 = n & 1023, h = c1 >> 6, dd = c1 & 63;
                    int bidx = m >> 11, t = m & 2047;
                    int bhn = bidx * 16 + h;
                    if (part == 0) { f0 *= 0.125f; f1 *= 0.125f; }
                    if (part < 2) {
                        uint32_t hp = packbf(f0, f1), lp = packlo(hp, f0, f1);
                        size_t idx = ((size_t)bhn * Tt + t) * HD + dd;
                        __nv_bfloat16* dh = (part == 0) ? g_qh : g_kh;
                        __nv_bfloat16* dl = (part == 0) ? g_ql : g_kl;
                        *reinterpret_cast<uint32_t*>(dh + idx) = hp;
                        *reinterpret_cast<uint32_t*>(dl + idx) = lp;
                    } else {
                        // V transposed: [b,h,d,t]
                        __nv_bfloat16 h0 = __float2bfloat16(f0);
                        __nv_bfloat16 h1 = __float2bfloat16(f1);
                        size_t idx0 = ((size_t)bhn * HD + dd) * Tt + t;
                        g_vth[idx0]        = h0;
                        g_vth[idx0 + Tt]   = h1;
                        g_vtl[idx0]        = __float2bfloat16(f0 - __bfloat162float(h0));
                        g_vtl[idx0 + Tt]   = __float2bfloat16(f1 - __bfloat162float(h1));
                    }
                } else {
                    f0 += __ldg(bias + n);
                    f1 += __ldg(bias + n + 1);
                    float2 v = {f0, f1};
                    *reinterpret_cast<float2*>(out + (size_t)m * N + n) = v;
                }
            }
        }
}

// ---------------------------------------------------------------------------
// Tensor-core flash attention. CTA: 128 q-rows x (b,h). 8 warps x 16 rows.
// Key blocks of 128, cp.async double-buffered (Kh,Kl,Vth,Vtl / stage).
// S = QhKh + QhKl + QlKh; softmax in registers; P split hi/lo in-register;
// O += PhVh + PlVh + PhVl. Writes y as bf16 hi/lo for the proj GEMM.
// ---------------------------------------------------------------------------
__global__ __launch_bounds__(256, 1) void sa_attn_mma(const int* __restrict__ pad)
{
    extern __shared__ char smem[];
    __shared__ float pm[2][128];
    uint32_t sb = smem_u32(smem);
    int tid = threadIdx.x, lane = tid & 31, warp = tid >> 5;
    int qt = (int)gridDim.x - 1 - (int)blockIdx.x;   // big tiles first
    int bh = blockIdx.y, bb = bh >> 4, hh = bh & 15;
    int q0 = qt * 128;
    size_t kbase = (size_t)bh * Tt * HD;   // q/k layout [bh][t][d]
    size_t vbase = (size_t)bh * HD * Tt;   // vt layout  [bh][d][t]

    // ---- stage Q (hi/lo) into buf0, extract fragments ----
#pragma unroll
    for (int i = 0; i < 8; i++) {
        int id = tid + i * 256;            // 2048: arr x 128 rows x 8 chunks
        int arr = id >> 10, rem = id & 1023, row = rem >> 3, c = rem & 7;
        const __nv_bfloat16* src = (arr ? g_ql : g_qh) + kbase + (size_t)(q0 + row) * HD + c * 8;
        cpasync16(sb + arr * 16384 + row * 128 + ((c ^ (row & 7)) << 4), src);
    }
    CP_COMMIT();
    CP_WAIT0();
    __syncthreads();
    uint32_t qh[4][4], ql[4][4];
#pragma unroll
    for (int ks = 0; ks < 4; ks++) {
        int row = warp * 16 + (lane & 15), cch = ks * 2 + (lane >> 4);
        uint32_t off = row * 128 + ((cch ^ (row & 7)) << 4);
        ldsm4(qh[ks], sb + off);
        ldsm4(ql[ks], sb + 16384 + off);
    }
    __syncthreads();

    auto load_stage = [&](int st, int kt) {
        uint32_t sbase = sb + st * ASTAGE;
        int k0 = kt * 128;
#pragma unroll
        for (int i = 0; i < 8; i++) {      // K tiles: 128 rows x 8 chunks x2
            int id = tid + i * 256;
            int arr = id >> 10, rem = id & 1023, row = rem >> 3, c = rem & 7;
            const __nv_bfloat16* src = (arr ? g_kl : g_kh) + kbase + (size_t)(k0 + row) * HD + c * 8;
            cpasync16(sbase + arr * 16384 + row * 128 + ((c ^ (row & 7)) << 4), src);
        }
#pragma unroll
        for (int i = 0; i < 8; i++) {      // Vt tiles: 64 rows x 16 chunks x2
            int id = tid + i * 256;
            int arr = id >> 10, rem = id & 1023, row = rem >> 4, c = rem & 15;
            const __nv_bfloat16* src = (arr ? g_vtl : g_vth) + vbase + (size_t)row * Tt + k0 + c * 8;
            cpasync16(sbase + 32768 + arr * 16384 + row * 256 + ((c ^ (row & 7)) << 4), src);
        }
        if (tid < 128) pm[st][tid] = pad[bb * Tt + k0 + tid] ? 0.0f : -1e30f;
    };

    float o[8][4];
#pragma unroll
    for (int i = 0; i < 8; i++)
#pragma unroll
        for (int e = 0; e < 4; e++) o[i][e] = 0.0f;
    float mrow[2] = {-1e30f, -1e30f}, lrow[2] = {0.0f, 0.0f};

    load_stage(0, 0);
    CP_COMMIT();

    for (int kt = 0; kt <= qt; kt++) {
        if (kt < qt) load_stage((kt + 1) & 1, kt + 1);
        CP_COMMIT();
        CP_WAIT1();
        __syncthreads();
        uint32_t sbase = sb + (kt & 1) * ASTAGE;

        // ---- S = Q K^T (16 n8-tiles) ----
        float s[16][4];
#pragma unroll
        for (int nt = 0; nt < 16; nt++)
#pragma unroll
            for (int e = 0; e < 4; e++) s[nt][e] = 0.0f;

#pragma unroll
        for (int ntp = 0; ntp < 8; ntp++) {
#pragma unroll
            for (int ks = 0; ks < 4; ks++) {
                int row = ntp * 16 + (lane & 15), cch = ks * 2 + (lane >> 4);
                uint32_t off = row * 128 + ((cch ^ (row & 7)) << 4);
                uint32_t t[4], kh0[2], kh1[2], kl0[2], kl1[2];
                ldsm4(t, sbase + off);
                kh0[0] = t[0]; kh0[1] = t[2]; kh1[0] = t[1]; kh1[1] = t[3];
                ldsm4(t, sbase + 16384 + off);
                kl0[0] = t[0]; kl0[1] = t[2]; kl1[0] = t[1]; kl1[1] = t[3];
                mma16816(s[2 * ntp], qh[ks], kh0);
                mma16816(s[2 * ntp], qh[ks], kl0);
                mma16816(s[2 * ntp], ql[ks], kh0);
                mma16816(s[2 * ntp + 1], qh[ks], kh1);
                mma16816(s[2 * ntp + 1], qh[ks], kl1);
                mma16816(s[2 * ntp + 1], ql[ks], kh1);
            }
        }

        // ---- masks ----
        int c2 = 2 * (lane & 3);
#pragma unroll
        for (int nt = 0; nt < 16; nt++) {
            float m0v = pm[kt & 1][nt * 8 + c2];
            float m1v = pm[kt & 1][nt * 8 + c2 + 1];
            s[nt][0] += m0v; s[nt][1] += m1v; s[nt][2] += m0v; s[nt][3] += m1v;
        }
        if (kt == qt) {
            int r0 = warp * 16 + (lane >> 2), r1 = r0 + 8;
#pragma unroll
            for (int nt = 0; nt < 16; nt++) {
                int col0 = nt * 8 + c2;
                if (col0 > r0)     s[nt][0] = -1e30f;
                if (col0 + 1 > r0) s[nt][1] = -1e30f;
                if (col0 > r1)     s[nt][2] = -1e30f;
                if (col0 + 1 > r1) s[nt][3] = -1e30f;
            }
        }

        // ---- online softmax (2 rows per lane) ----
#pragma unroll
        for (int h2 = 0; h2 < 2; h2++) {
            float mt = -1e30f;
#pragma unroll
            for (int nt = 0; nt < 16; nt++)
                mt = fmaxf(mt, fmaxf(s[nt][2 * h2], s[nt][2 * h2 + 1]));
            mt = fmaxf(mt, __shfl_xor_sync(0xffffffffu, mt, 1));
            mt = fmaxf(mt, __shfl_xor_sync(0xffffffffu, mt, 2));
            float mnew = fmaxf(mrow[h2], mt);
            float alpha = __expf(mrow[h2] - mnew);
            float rs = 0.0f;
#pragma unroll
            for (int nt = 0; nt < 16; nt++) {
                s[nt][2 * h2]     = __expf(s[nt][2 * h2] - mnew);
                s[nt][2 * h2 + 1] = __expf(s[nt][2 * h2 + 1] - mnew);
                rs += s[nt][2 * h2] + s[nt][2 * h2 + 1];
            }
            rs += __shfl_xor_sync(0xffffffffu, rs, 1);
            rs += __shfl_xor_sync(0xffffffffu, rs, 2);
            lrow[h2] = lrow[h2] * alpha + rs;
            mrow[h2] = mnew;
#pragma unroll
            for (int dt = 0; dt < 8; dt++) {
                o[dt][2 * h2] *= alpha;
                o[dt][2 * h2 + 1] *= alpha;
            }
        }

        // ---- O += P V : P fragments re-packed from S accumulators ----
#pragma unroll
        for (int ksp = 0; ksp < 8; ksp++) {
            int t0 = 2 * ksp, t1 = 2 * ksp + 1;
            uint32_t ah[4], al[4];
            ah[0] = packbf(s[t0][0], s[t0][1]); al[0] = packlo(ah[0], s[t0][0], s[t0][1]);
            ah[1] = packbf(s[t0][2], s[t0][3]); al[1] = packlo(ah[1], s[t0][2], s[t0][3]);
            ah[2] = packbf(s[t1][0], s[t1][1]); al[2] = packlo(ah[2], s[t1][0], s[t1][1]);
            ah[3] = packbf(s[t1][2], s[t1][3]); al[3] = packlo(ah[3], s[t1][2], s[t1][3]);
#pragma unroll
            for (int ntv = 0; ntv < 4; ntv++) {
                int row = ntv * 16 + (lane & 15), cch = ksp * 2 + (lane >> 4);
                uint32_t off = row * 256 + ((cch ^ (row & 7)) << 4);
                uint32_t t[4], vh0[2], vh1[2], vl0[2], vl1[2];
                ldsm4(t, sbase + 32768 + off);
                vh0[0] = t[0]; vh0[1] = t[2]; vh1[0] = t[1]; vh1[1] = t[3];
                ldsm4(t, sbase + 49152 + off);
                vl0[0] = t[0]; vl0[1] = t[2]; vl1[0] = t[1]; vl1[1] = t[3];
                mma16816(o[2 * ntv], ah, vh0);
                mma16816(o[2 * ntv], al, vh0);
                mma16816(o[2 * ntv], ah, vl0);
                mma16816(o[2 * ntv + 1], ah, vh1);
                mma16816(o[2 * ntv + 1], al, vh1);
                mma16816(o[2 * ntv + 1], ah, vl1);
            }
        }
        __syncthreads();   // all reads of this stage done before it is refilled
    }

    // ---- normalize, split, write y (bf16 hi/lo) ----
    // Global y row = bb*Tt + t  (batch offset was the round-5 bug)
    float i0 = 1.0f / lrow[0], i1 = 1.0f / lrow[1];
    int r0 = bb * Tt + q0 + warp * 16 + (lane >> 2), r1 = r0 + 8;
#pragma unroll
    for (int dt = 0; dt < 8; dt++) {
        int col = hh * 64 + dt * 8 + 2 * (lane & 3);
        float f0 = o[dt][0] * i0, f1 = o[dt][1] * i0;
        uint32_t hp = packbf(f0, f1), lp = packlo(hp, f0, f1);
        *reinterpret_cast<uint32_t*>(gy_h + (size_t)r0 * Cc + col) = hp;
        *reinterpret_cast<uint32_t*>(gy_l + (size_t)r0 * Cc + col) = lp;
        float f2 = o[dt][2] * i1, f3 = o[dt][3] * i1;
        uint32_t hp2 = packbf(f2, f3), lp2 = packlo(hp2, f2, f3);
        *reinterpret_cast<uint32_t*>(gy_h + (size_t)r1 * Cc + col) = hp2;
        *reinterpret_cast<uint32_t*>(gy_l + (size_t)r1 * Cc + col) = lp2;
    }
}

// ---------------------------------------------------------------------------
extern "C" void kernel_launch(void* const* d_in, const int* in_sizes, int n_in,
                              void* d_out, int out_size)
{
    (void)in_sizes; (void)n_in; (void)out_size;
    const float* x      = (const float*)d_in[0];
    const int*   pad    = (const int*)d_in[1];
    const float* w_attn = (const float*)d_in[2];
    const float* w_proj = (const float*)d_in[3];
    const float* b_proj = (const float*)d_in[4];
    float* out = (float*)d_out;

    cudaFuncSetAttribute(sa_gemm_mma<0>, cudaFuncAttributeMaxDynamicSharedMemorySize, GSM_BYTES);
    cudaFuncSetAttribute(sa_gemm_mma<1>, cudaFuncAttributeMaxDynamicSharedMemorySize, GSM_BYTES);
    cudaFuncSetAttribute(sa_attn_mma,    cudaFuncAttributeMaxDynamicSharedMemorySize, ASM_BYTES);

    void *pxh, *pxl, *pyh, *pyl, *pwah, *pwal, *pwph, *pwpl;
    cudaGetSymbolAddress(&pxh, gx_h);  cudaGetSymbolAddress(&pxl, gx_l);
    cudaGetSymbolAddress(&pyh, gy_h);  cudaGetSymbolAddress(&pyl, gy_l);
    cudaGetSymbolAddress(&pwah, gwa_h); cudaGetSymbolAddress(&pwal, gwa_l);
    cudaGetSymbolAddress(&pwph, gwp_h); cudaGetSymbolAddress(&pwpl, gwp_l);

    // Split x; transpose+split weights
    k_split<<<(BT * Kd / 4 + 255) / 256, 256>>>(
        (const float4*)x, (__nv_bfloat162*)pxh, (__nv_bfloat162*)pxl, BT * Kd / 4);
    k_splitT<<<dim3(3072 / 32, Kd / 32), dim3(32, 8)>>>(
        w_attn, (__nv_bfloat16*)pwah, (__nv_bfloat16*)pwal, 3072);
    k_splitT<<<dim3(1024 / 32, Kd / 32), dim3(32, 8)>>>(
        w_proj, (__nv_bfloat16*)pwph, (__nv_bfloat16*)pwpl, 1024);

    // QKV projection (writes bf16 q/k and transposed v directly)
    sa_gemm_mma<0><<<dim3(3072 / 128, BT / 128), 256, GSM_BYTES>>>(
        (const __nv_bfloat16*)pxh, (const __nv_bfloat16*)pxl,
        (const __nv_bfloat16*)pwah, (const __nv_bfloat16*)pwal,
        nullptr, nullptr, 3072);

    // Tensor-core attention (writes y bf16 hi/lo)
    sa_attn_mma<<<dim3(Tt / 128, Bb * Hh), 256, ASM_BYTES>>>(pad);

    // Output projection + bias
    sa_gemm_mma<1><<<dim3(1024 / 128, BT / 128), 256, GSM_BYTES>>>(
        (const __nv_bfloat16*)pyh, (const __nv_bfloat16*)pyl,
        (const __nv_bfloat16*)pwph, (const __nv_bfloat16*)pwpl,
        b_proj, out, 1024);
}

// round 7
// speedup vs baseline: 2.7040x; 1.0036x over previous
#include <cuda_runtime.h>
#include <cuda_bf16.h>
#include <cstdint>

typedef unsigned long long u64;

__device__ __forceinline__ uint32_t smem_u32(const void* p) {
    uint32_t a;
    asm("{ .reg .u64 t; cvta.to.shared.u64 t, %1; cvt.u32.u64 %0, t; }" : "=r"(a) : "l"(p));
    return a;
}
__device__ __forceinline__ void ldsm4(uint32_t* r, uint32_t addr) {
    asm volatile("ldmatrix.sync.aligned.m8n8.x4.shared.b16 {%0,%1,%2,%3}, [%4];"
                 : "=r"(r[0]), "=r"(r[1]), "=r"(r[2]), "=r"(r[3]) : "r"(addr));
}
__device__ __forceinline__ void mma16816(float* d, const uint32_t* a, const uint32_t* b) {
    asm volatile(
        "mma.sync.aligned.m16n8k16.row.col.f32.bf16.bf16.f32 "
        "{%0,%1,%2,%3}, {%4,%5,%6,%7}, {%8,%9}, {%0,%1,%2,%3};"
        : "+f"(d[0]), "+f"(d[1]), "+f"(d[2]), "+f"(d[3])
        : "r"(a[0]), "r"(a[1]), "r"(a[2]), "r"(a[3]), "r"(b[0]), "r"(b[1]));
}
__device__ __forceinline__ void cpasync16(uint32_t dst, const void* src) {
    asm volatile("cp.async.cg.shared.global [%0], [%1], 16;" :: "r"(dst), "l"(src));
}
#define CP_COMMIT() asm volatile("cp.async.commit_group;" ::: "memory")
#define CP_WAIT1()  asm volatile("cp.async.wait_group 1;" ::: "memory")
#define CP_WAIT0()  asm volatile("cp.async.wait_group 0;" ::: "memory")

// pack 2 floats -> bf16x2 (lo in low half)
__device__ __forceinline__ uint32_t packbf(float lo, float hi) {
    uint32_t d;
    asm("cvt.rn.bf16x2.f32 %0, %1, %2;" : "=r"(d) : "f"(hi), "f"(lo));
    return d;
}
__device__ __forceinline__ uint32_t packlo(uint32_t hpk, float lo, float hi) {
    float h0 = __uint_as_float(hpk << 16);
    float h1 = __uint_as_float(hpk & 0xffff0000u);
    return packbf(lo - h0, hi - h1);
}

// ---------------- problem constants ----------------
constexpr int Bb = 4, Tt = 2048, Cc = 1024, Hh = 16, HD = 64;
constexpr int BT = Bb * Tt;
constexpr int Kd = 1024;
// GEMM: BK=32 -> 4 tiles x 8KB per stage; double buffer = 64KB -> 2 CTAs/SM
constexpr int GTILE = 8192;
constexpr int STAGE = 4 * GTILE;       // 32768
constexpr int GSM_BYTES = 2 * STAGE;   // 65536
constexpr int ASTAGE = 65536;          // attn: Kh,Kl,Vth,Vtl x 16KB
constexpr int ASM_BYTES = 2 * ASTAGE;

// ---------------- scratch (device globals) ----------------
constexpr size_t QKV = (size_t)Bb * Hh * Tt * HD;   // 8388608
__device__ __nv_bfloat16 g_qh[QKV], g_ql[QKV];      // [b,h,t,d], q pre-scaled 0.125
__device__ __nv_bfloat16 g_kh[QKV], g_kl[QKV];      // [b,h,t,d]
__device__ __nv_bfloat16 g_vth[QKV], g_vtl[QKV];    // [b,h,d,t]  (transposed V)
__device__ __nv_bfloat16 gx_h[(size_t)BT * Kd],  gx_l[(size_t)BT * Kd];
__device__ __nv_bfloat16 gy_h[(size_t)BT * Kd],  gy_l[(size_t)BT * Kd];
__device__ __nv_bfloat16 gwa_h[(size_t)3072 * Kd], gwa_l[(size_t)3072 * Kd];
__device__ __nv_bfloat16 gwp_h[(size_t)1024 * Kd], gwp_l[(size_t)1024 * Kd];

// ---------------- conversion kernels ----------------
__global__ void k_split(const float4* __restrict__ src, __nv_bfloat162* __restrict__ h,
                        __nv_bfloat162* __restrict__ l, int n4)
{
    int i = blockIdx.x * blockDim.x + threadIdx.x;
    if (i >= n4) return;
    float4 v = src[i];
    __nv_bfloat16 h0 = __float2bfloat16(v.x), h1 = __float2bfloat16(v.y);
    __nv_bfloat16 h2 = __float2bfloat16(v.z), h3 = __float2bfloat16(v.w);
    h[i * 2]     = __halves2bfloat162(h0, h1);
    h[i * 2 + 1] = __halves2bfloat162(h2, h3);
    l[i * 2]     = __halves2bfloat162(__float2bfloat16(v.x - __bfloat162float(h0)),
                                      __float2bfloat16(v.y - __bfloat162float(h1)));
    l[i * 2 + 1] = __halves2bfloat162(__float2bfloat16(v.z - __bfloat162float(h2)),
                                      __float2bfloat16(v.w - __bfloat162float(h3)));
}

__global__ void k_splitT(const float* __restrict__ src, __nv_bfloat16* __restrict__ h,
                         __nv_bfloat16* __restrict__ l, int Ncols)
{
    __shared__ float ts[32][33];
    int tx = threadIdx.x, ty = threadIdx.y;
    int c0 = blockIdx.x * 32, r0 = blockIdx.y * 32;
#pragma unroll
    for (int i = 0; i < 4; i++)
        ts[ty + i * 8][tx] = src[(size_t)(r0 + ty + i * 8) * Ncols + c0 + tx];
    __syncthreads();
#pragma unroll
    for (int i = 0; i < 4; i++) {
        int n = c0 + ty + i * 8, k = r0 + tx;
        float v = ts[tx][ty + i * 8];
        __nv_bfloat16 hv = __float2bfloat16(v);
        h[(size_t)n * 1024 + k] = hv;
        l[(size_t)n * 1024 + k] = __float2bfloat16(v - __bfloat162float(hv));
    }
}

// ---------------------------------------------------------------------------
// mma.sync bf16-split GEMM. BK=32, 64B-pitch tiles, swizzle off ^= (off>>3)&0x30,
// double-buffered cp.async, 2 CTAs/SM.
// MODE 0: q/k bf16 hi/lo [b,h,t,d]; V^T hi/lo [b,h,d,t] via smem-staged transpose.
// MODE 1: fp32 out + bias.
// ---------------------------------------------------------------------------
template <int MODE>
__global__ __launch_bounds__(256, 2) void sa_gemm_mma(
    const __nv_bfloat16* __restrict__ Ah, const __nv_bfloat16* __restrict__ Al,
    const __nv_bfloat16* __restrict__ Bh, const __nv_bfloat16* __restrict__ Bl,
    const float* __restrict__ bias, float* __restrict__ out, int N)
{
    extern __shared__ char smem[];
    uint32_t sb = smem_u32(smem);
    int tid = threadIdx.x, lane = tid & 31, warp = tid >> 5;
    int m0 = blockIdx.y * 128, n0 = blockIdx.x * 128;
    int wm = (warp >> 2) * 64, wn = (warp & 3) * 32;

    const __nv_bfloat16* srcs[4] = {Ah, Al, Bh, Bl};

    auto load_stage = [&](int st, int c) {
        uint32_t sbase = sb + st * STAGE;
        int kc0 = c * 32;
#pragma unroll
        for (int i = 0; i < 8; i++) {
            int id = tid + i * 256;            // 2048 16B chunks
            int tile = id >> 9, rem = id & 511;
            int row = rem >> 2, cch = rem & 3;
            const __nv_bfloat16* src = srcs[tile] + (size_t)(((tile < 2) ? m0 : n0) + row) * Kd + kc0 + cch * 8;
            uint32_t off = row * 64 + cch * 16;
            off ^= ((off >> 3) & 0x30);
            cpasync16(sbase + tile * GTILE + off, src);
        }
    };

    float acc[4][4][4];
#pragma unroll
    for (int a = 0; a < 4; a++)
#pragma unroll
        for (int b = 0; b < 4; b++)
#pragma unroll
            for (int e = 0; e < 4; e++) acc[a][b][e] = 0.0f;

    load_stage(0, 0);
    CP_COMMIT();

    for (int c = 0; c < 32; c++) {
        if (c + 1 < 32) load_stage((c + 1) & 1, c + 1);
        CP_COMMIT();
        CP_WAIT1();
        __syncthreads();
        uint32_t sbase = sb + (c & 1) * STAGE;
#pragma unroll
        for (int ks = 0; ks < 2; ks++) {
            uint32_t ah[4][4], al[4][4], bh[4][2], bl[4][2];
#pragma unroll
            for (int mt = 0; mt < 4; mt++) {
                int row = wm + mt * 16 + (lane & 15);
                int cch = ks * 2 + (lane >> 4);
                uint32_t off = row * 64 + cch * 16;
                off ^= ((off >> 3) & 0x30);
                ldsm4(ah[mt], sbase + off);
                ldsm4(al[mt], sbase + GTILE + off);
            }
#pragma unroll
            for (int nt = 0; nt < 2; nt++) {
                int row = wn + nt * 16 + (lane & 15);
                int cch = ks * 2 + (lane >> 4);
                uint32_t off = row * 64 + cch * 16;
                off ^= ((off >> 3) & 0x30);
                uint32_t t[4];
                ldsm4(t, sbase + 2 * GTILE + off);
                bh[nt * 2][0] = t[0]; bh[nt * 2][1] = t[2];
                bh[nt * 2 + 1][0] = t[1]; bh[nt * 2 + 1][1] = t[3];
                ldsm4(t, sbase + 3 * GTILE + off);
                bl[nt * 2][0] = t[0]; bl[nt * 2][1] = t[2];
                bl[nt * 2 + 1][0] = t[1]; bl[nt * 2 + 1][1] = t[3];
            }
#pragma unroll
            for (int mt = 0; mt < 4; mt++)
#pragma unroll
                for (int j = 0; j < 4; j++) {
                    mma16816(acc[mt][j], ah[mt], bh[j]);
                    mma16816(acc[mt][j], ah[mt], bl[j]);
                    mma16816(acc[mt][j], al[mt], bh[j]);
                }
        }
        __syncthreads();
    }

    if (MODE == 0 && n0 >= 2048) {
        // ---- V CTA: smem-staged transpose -> coalesced [b,h,d,t] stores ----
        // Two passes over the two head-halves of this 128-col tile.
        constexpr int PITCH = 136;   // elements; 272B rows (16B aligned, conflict-spread)
        __nv_bfloat16* svh = reinterpret_cast<__nv_bfloat16*>(smem);
        __nv_bfloat16* svl = svh + 64 * PITCH;
        int bidx = m0 >> 11, tbase = m0 & 2047;
#pragma unroll
        for (int hl = 0; hl < 2; hl++) {
            if (hl) __syncthreads();
#pragma unroll
            for (int mt = 0; mt < 4; mt++)
#pragma unroll
                for (int j = 0; j < 4; j++) {
                    int n = n0 + wn + j * 8 + (lane & 3) * 2;
                    if (((n >> 6) & 1) != hl) continue;
                    int dd = n & 63;
#pragma unroll
                    for (int half = 0; half < 2; half++) {
                        int tl = wm + mt * 16 + (lane >> 2) + half * 8;
                        float f0 = acc[mt][j][half * 2], f1 = acc[mt][j][half * 2 + 1];
                        __nv_bfloat16 h0 = __float2bfloat16(f0);
                        __nv_bfloat16 h1 = __float2bfloat16(f1);
                        svh[dd * PITCH + tl]       = h0;
                        svh[(dd + 1) * PITCH + tl] = h1;
                        svl[dd * PITCH + tl]       = __float2bfloat16(f0 - __bfloat162float(h0));
                        svl[(dd + 1) * PITCH + tl] = __float2bfloat16(f1 - __bfloat162float(h1));
                    }
                }
            __syncthreads();
            int h = ((n0 & 1023) >> 6) + hl;
            int bhn = bidx * 16 + h;
#pragma unroll
            for (int i = 0; i < 8; i++) {
                int id = tid + i * 256;          // 2048: arr x 64 dd x 16 tc
                int arr = id >> 10, rem = id & 1023, dd = rem >> 4, tc = rem & 15;
                const __nv_bfloat16* s = (arr ? svl : svh) + dd * PITCH + tc * 8;
                uint4 v = *reinterpret_cast<const uint4*>(s);
                __nv_bfloat16* dst = (arr ? g_vtl : g_vth) +
                    (((size_t)bhn * HD + dd) * Tt + tbase + tc * 8);
                *reinterpret_cast<uint4*>(dst) = v;
            }
        }
        return;
    }

#pragma unroll
    for (int mt = 0; mt < 4; mt++)
#pragma unroll
        for (int j = 0; j < 4; j++) {
            int n = n0 + wn + j * 8 + (lane & 3) * 2;
            int mA = m0 + wm + mt * 16 + (lane >> 2);
#pragma unroll
            for (int half = 0; half < 2; half++) {
                int m = mA + half * 8;
                float f0 = acc[mt][j][half * 2], f1 = acc[mt][j][half * 2 + 1];
                if (MODE == 0) {
                    int part = n >> 10, c1 = n & 1023, h = c1 >> 6, dd = c1 & 63;
                    int bidx = m >> 11, t = m & 2047;
                    int bhn = bidx * 16 + h;
                    if (part == 0) { f0 *= 0.125f; f1 *= 0.125f; }
                    uint32_t hp = packbf(f0, f1), lp = packlo(hp, f0, f1);
                    size_t idx = ((size_t)bhn * Tt + t) * HD + dd;
                    __nv_bfloat16* dh = (part == 0) ? g_qh : g_kh;
                    __nv_bfloat16* dl = (part == 0) ? g_ql : g_kl;
                    *reinterpret_cast<uint32_t*>(dh + idx) = hp;
                    *reinterpret_cast<uint32_t*>(dl + idx) = lp;
                } else {
                    f0 += __ldg(bias + n);
                    f1 += __ldg(bias + n + 1);
                    float2 v = {f0, f1};
                    *reinterpret_cast<float2*>(out + (size_t)m * N + n) = v;
                }
            }
        }
}

// ---------------------------------------------------------------------------
// Tensor-core flash attention (round-6 verified). 128 q-rows x (b,h), 8 warps.
// ---------------------------------------------------------------------------
__global__ __launch_bounds__(256, 1) void sa_attn_mma(const int* __restrict__ pad)
{
    extern __shared__ char smem[];
    __shared__ float pm[2][128];
    uint32_t sb = smem_u32(smem);
    int tid = threadIdx.x, lane = tid & 31, warp = tid >> 5;
    int qt = (int)gridDim.x - 1 - (int)blockIdx.x;   // big tiles first
    int bh = blockIdx.y, bb = bh >> 4, hh = bh & 15;
    int q0 = qt * 128;
    size_t kbase = (size_t)bh * Tt * HD;
    size_t vbase = (size_t)bh * HD * Tt;

#pragma unroll
    for (int i = 0; i < 8; i++) {
        int id = tid + i * 256;
        int arr = id >> 10, rem = id & 1023, row = rem >> 3, c = rem & 7;
        const __nv_bfloat16* src = (arr ? g_ql : g_qh) + kbase + (size_t)(q0 + row) * HD + c * 8;
        cpasync16(sb + arr * 16384 + row * 128 + ((c ^ (row & 7)) << 4), src);
    }
    CP_COMMIT();
    CP_WAIT0();
    __syncthreads();
    uint32_t qh[4][4], ql[4][4];
#pragma unroll
    for (int ks = 0; ks < 4; ks++) {
        int row = warp * 16 + (lane & 15), cch = ks * 2 + (lane >> 4);
        uint32_t off = row * 128 + ((cch ^ (row & 7)) << 4);
        ldsm4(qh[ks], sb + off);
        ldsm4(ql[ks], sb + 16384 + off);
    }
    __syncthreads();

    auto load_stage = [&](int st, int kt) {
        uint32_t sbase = sb + st * ASTAGE;
        int k0 = kt * 128;
#pragma unroll
        for (int i = 0; i < 8; i++) {
            int id = tid + i * 256;
            int arr = id >> 10, rem = id & 1023, row = rem >> 3, c = rem & 7;
            const __nv_bfloat16* src = (arr ? g_kl : g_kh) + kbase + (size_t)(k0 + row) * HD + c * 8;
            cpasync16(sbase + arr * 16384 + row * 128 + ((c ^ (row & 7)) << 4), src);
        }
#pragma unroll
        for (int i = 0; i < 8; i++) {
            int id = tid + i * 256;
            int arr = id >> 10, rem = id & 1023, row = rem >> 4, c = rem & 15;
            const __nv_bfloat16* src = (arr ? g_vtl : g_vth) + vbase + (size_t)row * Tt + k0 + c * 8;
            cpasync16(sbase + 32768 + arr * 16384 + row * 256 + ((c ^ (row & 7)) << 4), src);
        }
        if (tid < 128) pm[st][tid] = pad[bb * Tt + k0 + tid] ? 0.0f : -1e30f;
    };

    float o[8][4];
#pragma unroll
    for (int i = 0; i < 8; i++)
#pragma unroll
        for (int e = 0; e < 4; e++) o[i][e] = 0.0f;
    float mrow[2] = {-1e30f, -1e30f}, lrow[2] = {0.0f, 0.0f};

    load_stage(0, 0);
    CP_COMMIT();

    for (int kt = 0; kt <= qt; kt++) {
        if (kt < qt) load_stage((kt + 1) & 1, kt + 1);
        CP_COMMIT();
        CP_WAIT1();
        __syncthreads();
        uint32_t sbase = sb + (kt & 1) * ASTAGE;

        float s[16][4];
#pragma unroll
        for (int nt = 0; nt < 16; nt++)
#pragma unroll
            for (int e = 0; e < 4; e++) s[nt][e] = 0.0f;

#pragma unroll
        for (int ntp = 0; ntp < 8; ntp++) {
#pragma unroll
            for (int ks = 0; ks < 4; ks++) {
                int row = ntp * 16 + (lane & 15), cch = ks * 2 + (lane >> 4);
                uint32_t off = row * 128 + ((cch ^ (row & 7)) << 4);
                uint32_t t[4], kh0[2], kh1[2], kl0[2], kl1[2];
                ldsm4(t, sbase + off);
                kh0[0] = t[0]; kh0[1] = t[2]; kh1[0] = t[1]; kh1[1] = t[3];
                ldsm4(t, sbase + 16384 + off);
                kl0[0] = t[0]; kl0[1] = t[2]; kl1[0] = t[1]; kl1[1] = t[3];
                mma16816(s[2 * ntp], qh[ks], kh0);
                mma16816(s[2 * ntp], qh[ks], kl0);
                mma16816(s[2 * ntp], ql[ks], kh0);
                mma16816(s[2 * ntp + 1], qh[ks], kh1);
                mma16816(s[2 * ntp + 1], qh[ks], kl1);
                mma16816(s[2 * ntp + 1], ql[ks], kh1);
            }
        }

        int c2 = 2 * (lane & 3);
#pragma unroll
        for (int nt = 0; nt < 16; nt++) {
            float m0v = pm[kt & 1][nt * 8 + c2];
            float m1v = pm[kt & 1][nt * 8 + c2 + 1];
            s[nt][0] += m0v; s[nt][1] += m1v; s[nt][2] += m0v; s[nt][3] += m1v;
        }
        if (kt == qt) {
            int r0 = warp * 16 + (lane >> 2), r1 = r0 + 8;
#pragma unroll
            for (int nt = 0; nt < 16; nt++) {
                int col0 = nt * 8 + c2;
                if (col0 > r0)     s[nt][0] = -1e30f;
                if (col0 + 1 > r0) s[nt][1] = -1e30f;
                if (col0 > r1)     s[nt][2] = -1e30f;
                if (col0 + 1 > r1) s[nt][3] = -1e30f;
            }
        }

#pragma unroll
        for (int h2 = 0; h2 < 2; h2++) {
            float mt = -1e30f;
#pragma unroll
            for (int nt = 0; nt < 16; nt++)
                mt = fmaxf(mt, fmaxf(s[nt][2 * h2], s[nt][2 * h2 + 1]));
            mt = fmaxf(mt, __shfl_xor_sync(0xffffffffu, mt, 1));
            mt = fmaxf(mt, __shfl_xor_sync(0xffffffffu, mt, 2));
            float mnew = fmaxf(mrow[h2], mt);
            float alpha = __expf(mrow[h2] - mnew);
            float rs = 0.0f;
#pragma unroll
            for (int nt = 0; nt < 16; nt++) {
                s[nt][2 * h2]     = __expf(s[nt][2 * h2] - mnew);
                s[nt][2 * h2 + 1] = __expf(s[nt][2 * h2 + 1] - mnew);
                rs += s[nt][2 * h2] + s[nt][2 * h2 + 1];
            }
            rs += __shfl_xor_sync(0xffffffffu, rs, 1);
            rs += __shfl_xor_sync(0xffffffffu, rs, 2);
            lrow[h2] = lrow[h2] * alpha + rs;
            mrow[h2] = mnew;
#pragma unroll
            for (int dt = 0; dt < 8; dt++) {
                o[dt][2 * h2] *= alpha;
                o[dt][2 * h2 + 1] *= alpha;
            }
        }

#pragma unroll
        for (int ksp = 0; ksp < 8; ksp++) {
            int t0 = 2 * ksp, t1 = 2 * ksp + 1;
            uint32_t ah[4], al[4];
            ah[0] = packbf(s[t0][0], s[t0][1]); al[0] = packlo(ah[0], s[t0][0], s[t0][1]);
            ah[1] = packbf(s[t0][2], s[t0][3]); al[1] = packlo(ah[1], s[t0][2], s[t0][3]);
            ah[2] = packbf(s[t1][0], s[t1][1]); al[2] = packlo(ah[2], s[t1][0], s[t1][1]);
            ah[3] = packbf(s[t1][2], s[t1][3]); al[3] = packlo(ah[3], s[t1][2], s[t1][3]);
#pragma unroll
            for (int ntv = 0; ntv < 4; ntv++) {
                int row = ntv * 16 + (lane & 15), cch = ksp * 2 + (lane >> 4);
                uint32_t off = row * 256 + ((cch ^ (row & 7)) << 4);
                uint32_t t[4], vh0[2], vh1[2], vl0[2], vl1[2];
                ldsm4(t, sbase + 32768 + off);
                vh0[0] = t[0]; vh0[1] = t[2]; vh1[0] = t[1]; vh1[1] = t[3];
                ldsm4(t, sbase + 49152 + off);
                vl0[0] = t[0]; vl0[1] = t[2]; vl1[0] = t[1]; vl1[1] = t[3];
                mma16816(o[2 * ntv], ah, vh0);
                mma16816(o[2 * ntv], al, vh0);
                mma16816(o[2 * ntv], ah, vl0);
                mma16816(o[2 * ntv + 1], ah, vh1);
                mma16816(o[2 * ntv + 1], al, vh1);
                mma16816(o[2 * ntv + 1], ah, vl1);
            }
        }
        __syncthreads();
    }

    float i0 = 1.0f / lrow[0], i1 = 1.0f / lrow[1];
    int r0 = bb * Tt + q0 + warp * 16 + (lane >> 2), r1 = r0 + 8;
#pragma unroll
    for (int dt = 0; dt < 8; dt++) {
        int col = hh * 64 + dt * 8 + 2 * (lane & 3);
        float f0 = o[dt][0] * i0, f1 = o[dt][1] * i0;
        uint32_t hp = packbf(f0, f1), lp = packlo(hp, f0, f1);
        *reinterpret_cast<uint32_t*>(gy_h + (size_t)r0 * Cc + col) = hp;
        *reinterpret_cast<uint32_t*>(gy_l + (size_t)r0 * Cc + col) = lp;
        float f2 = o[dt][2] * i1, f3 = o[dt][3] * i1;
        uint32_t hp2 = packbf(f2, f3), lp2 = packlo(hp2, f2, f3);
        *reinterpret_cast<uint32_t*>(gy_h + (size_t)r1 * Cc + col) = hp2;
        *reinterpret_cast<uint32_t*>(gy_l + (size_t)r1 * Cc + col) = lp2;
    }
}

// ---------------------------------------------------------------------------
extern "C" void kernel_launch(void* const* d_in, const int* in_sizes, int n_in,
                              void* d_out, int out_size)
{
    (void)in_sizes; (void)n_in; (void)out_size;
    const float* x      = (const float*)d_in[0];
    const int*   pad    = (const int*)d_in[1];
    const float* w_attn = (const float*)d_in[2];
    const float* w_proj = (const float*)d_in[3];
    const float* b_proj = (const float*)d_in[4];
    float* out = (float*)d_out;

    cudaFuncSetAttribute(sa_gemm_mma<0>, cudaFuncAttributeMaxDynamicSharedMemorySize, GSM_BYTES);
    cudaFuncSetAttribute(sa_gemm_mma<1>, cudaFuncAttributeMaxDynamicSharedMemorySize, GSM_BYTES);
    cudaFuncSetAttribute(sa_attn_mma,    cudaFuncAttributeMaxDynamicSharedMemorySize, ASM_BYTES);

    void *pxh, *pxl, *pyh, *pyl, *pwah, *pwal, *pwph, *pwpl;
    cudaGetSymbolAddress(&pxh, gx_h);  cudaGetSymbolAddress(&pxl, gx_l);
    cudaGetSymbolAddress(&pyh, gy_h);  cudaGetSymbolAddress(&pyl, gy_l);
    cudaGetSymbolAddress(&pwah, gwa_h); cudaGetSymbolAddress(&pwal, gwa_l);
    cudaGetSymbolAddress(&pwph, gwp_h); cudaGetSymbolAddress(&pwpl, gwp_l);

    k_split<<<(BT * Kd / 4 + 255) / 256, 256>>>(
        (const float4*)x, (__nv_bfloat162*)pxh, (__nv_bfloat162*)pxl, BT * Kd / 4);
    k_splitT<<<dim3(3072 / 32, Kd / 32), dim3(32, 8)>>>(
        w_attn, (__nv_bfloat16*)pwah, (__nv_bfloat16*)pwal, 3072);
    k_splitT<<<dim3(1024 / 32, Kd / 32), dim3(32, 8)>>>(
        w_proj, (__nv_bfloat16*)pwph, (__nv_bfloat16*)pwpl, 1024);

    sa_gemm_mma<0><<<dim3(3072 / 128, BT / 128), 256, GSM_BYTES>>>(
        (const __nv_bfloat16*)pxh, (const __nv_bfloat16*)pxl,
        (const __nv_bfloat16*)pwah, (const __nv_bfloat16*)pwal,
        nullptr, nullptr, 3072);

    sa_attn_mma<<<dim3(Tt / 128, Bb * Hh), 256, ASM_BYTES>>>(pad);

    sa_gemm_mma<1><<<dim3(1024 / 128, BT / 128), 256, GSM_BYTES>>>(
        (const __nv_bfloat16*)pyh, (const __nv_bfloat16*)pyl,
        (const __nv_bfloat16*)pwph, (const __nv_bfloat16*)pwpl,
        b_proj, out, 1024);
}

// round 8
// speedup vs baseline: 4.0005x; 1.4795x over previous
#include <cuda_runtime.h>
#include <cuda_fp16.h>
#include <cstdint>

typedef unsigned long long u64;

__device__ __forceinline__ uint32_t smem_u32(const void* p) {
    uint32_t a;
    asm("{ .reg .u64 t; cvta.to.shared.u64 t, %1; cvt.u32.u64 %0, t; }" : "=r"(a) : "l"(p));
    return a;
}
__device__ __forceinline__ void ldsm4(uint32_t* r, uint32_t addr) {
    asm volatile("ldmatrix.sync.aligned.m8n8.x4.shared.b16 {%0,%1,%2,%3}, [%4];"
                 : "=r"(r[0]), "=r"(r[1]), "=r"(r[2]), "=r"(r[3]) : "r"(addr));
}
__device__ __forceinline__ void mma16816(float* d, const uint32_t* a, const uint32_t* b) {
    asm volatile(
        "mma.sync.aligned.m16n8k16.row.col.f32.f16.f16.f32 "
        "{%0,%1,%2,%3}, {%4,%5,%6,%7}, {%8,%9}, {%0,%1,%2,%3};"
        : "+f"(d[0]), "+f"(d[1]), "+f"(d[2]), "+f"(d[3])
        : "r"(a[0]), "r"(a[1]), "r"(a[2]), "r"(a[3]), "r"(b[0]), "r"(b[1]));
}
__device__ __forceinline__ void cpasync16(uint32_t dst, const void* src) {
    asm volatile("cp.async.cg.shared.global [%0], [%1], 16;" :: "r"(dst), "l"(src));
}
#define CP_COMMIT() asm volatile("cp.async.commit_group;" ::: "memory")
#define CP_WAIT1()  asm volatile("cp.async.wait_group 1;" ::: "memory")
#define CP_WAIT0()  asm volatile("cp.async.wait_group 0;" ::: "memory")

// pack 2 floats -> half2 bits (lo in low half)
__device__ __forceinline__ uint32_t packh(float lo, float hi) {
    __half2 h = __floats2half2_rn(lo, hi);
    return *reinterpret_cast<uint32_t*>(&h);
}
// residual pack: (lo,hi) minus their fp16 hi-parts
__device__ __forceinline__ uint32_t packhlo(uint32_t hp, float lo, float hi) {
    __half2 h = *reinterpret_cast<__half2*>(&hp);
    return packh(lo - __low2float(h), hi - __high2float(h));
}

// ---------------- problem constants ----------------
constexpr int Bb = 4, Tt = 2048, Cc = 1024, Hh = 16, HD = 64;
constexpr int BT = Bb * Tt;
constexpr int Kd = 1024;
// GEMM: BK=64, 3 tiles (Ah, Al, Bh) x 16KB per stage; double buffer = 96KB
constexpr int GTILE = 16384;
constexpr int STAGE = 3 * GTILE;       // 49152
constexpr int GSM_BYTES = 2 * STAGE;   // 98304
// attention: Kh (16KB) + Vth (16KB) per stage; double buffer = 64KB
constexpr int ASTAGE = 32768;
constexpr int ASM_BYTES = 2 * ASTAGE;

// ---------------- scratch (device globals) ----------------
constexpr size_t QKV = (size_t)Bb * Hh * Tt * HD;   // 8388608
__device__ __half g_qh[QKV], g_ql[QKV];             // [b,h,t,d], q pre-scaled 0.125
__device__ __half g_kh[QKV];                        // [b,h,t,d] single fp16
__device__ __half g_vth[QKV];                       // [b,h,d,t] single fp16 (transposed)
__device__ __half gx_h[(size_t)BT * Kd],  gx_l[(size_t)BT * Kd];
__device__ __half gy_h[(size_t)BT * Kd],  gy_l[(size_t)BT * Kd];
__device__ __half gwa_h[(size_t)3072 * Kd];         // w_attn^T single fp16
__device__ __half gwp_h[(size_t)1024 * Kd];         // w_proj^T single fp16

// ---------------- conversion kernels ----------------
__global__ void k_split(const float4* __restrict__ src, __half2* __restrict__ h,
                        __half2* __restrict__ l, int n4)
{
    int i = blockIdx.x * blockDim.x + threadIdx.x;
    if (i >= n4) return;
    float4 v = src[i];
    __half2 h0 = __floats2half2_rn(v.x, v.y);
    __half2 h1 = __floats2half2_rn(v.z, v.w);
    h[i * 2]     = h0;
    h[i * 2 + 1] = h1;
    l[i * 2]     = __floats2half2_rn(v.x - __low2float(h0), v.y - __high2float(h0));
    l[i * 2 + 1] = __floats2half2_rn(v.z - __low2float(h1), v.w - __high2float(h1));
}

// transpose: src[1024][Ncols] fp32 -> out[Ncols][1024] single fp16
__global__ void k_splitT(const float* __restrict__ src, __half* __restrict__ h, int Ncols)
{
    __shared__ float ts[32][33];
    int tx = threadIdx.x, ty = threadIdx.y;
    int c0 = blockIdx.x * 32, r0 = blockIdx.y * 32;
#pragma unroll
    for (int i = 0; i < 4; i++)
        ts[ty + i * 8][tx] = src[(size_t)(r0 + ty + i * 8) * Ncols + c0 + tx];
    __syncthreads();
#pragma unroll
    for (int i = 0; i < 4; i++) {
        int n = c0 + ty + i * 8, k = r0 + tx;
        h[(size_t)n * 1024 + k] = __float2half_rn(ts[tx][ty + i * 8]);
    }
}

// ---------------------------------------------------------------------------
// mma.sync fp16 2-term GEMM: D = Ah*Bh^T + Al*Bh^T (B single fp16).
// BK=64, 128B-pitch tiles, 0x70 swizzle, cp.async double-buffered, 2 CTAs/SM.
// MODE 0: q split hi/lo, k single, V^T single via smem transpose.
// MODE 1: fp32 out + bias.
// ---------------------------------------------------------------------------
template <int MODE>
__global__ __launch_bounds__(256, 2) void sa_gemm_mma(
    const __half* __restrict__ Ah, const __half* __restrict__ Al,
    const __half* __restrict__ Bh,
    const float* __restrict__ bias, float* __restrict__ out, int N)
{
    extern __shared__ char smem[];
    uint32_t sb = smem_u32(smem);
    int tid = threadIdx.x, lane = tid & 31, warp = tid >> 5;
    int m0 = blockIdx.y * 128, n0 = blockIdx.x * 128;
    int wm = (warp >> 2) * 64, wn = (warp & 3) * 32;

    const __half* srcs[3] = {Ah, Al, Bh};

    auto load_stage = [&](int st, int c) {
        uint32_t sbase = sb + st * STAGE;
        int kc0 = c * 64;
#pragma unroll
        for (int i = 0; i < 12; i++) {
            int id = tid + i * 256;            // 3072 16B chunks
            int tile = id >> 10, rem = id & 1023;
            int row = rem >> 3, cch = rem & 7;
            const __half* src = srcs[tile] + (size_t)(((tile < 2) ? m0 : n0) + row) * Kd + kc0 + cch * 8;
            uint32_t off = row * 128 + cch * 16;
            off ^= ((off >> 3) & 0x70);
            cpasync16(sbase + tile * GTILE + off, src);
        }
    };

    float acc[4][4][4];
#pragma unroll
    for (int a = 0; a < 4; a++)
#pragma unroll
        for (int b = 0; b < 4; b++)
#pragma unroll
            for (int e = 0; e < 4; e++) acc[a][b][e] = 0.0f;

    load_stage(0, 0);
    CP_COMMIT();

    for (int c = 0; c < 16; c++) {
        if (c + 1 < 16) load_stage((c + 1) & 1, c + 1);
        CP_COMMIT();
        CP_WAIT1();
        __syncthreads();
        uint32_t sbase = sb + (c & 1) * STAGE;
#pragma unroll
        for (int ks = 0; ks < 4; ks++) {
            uint32_t ah[4][4], al[4][4], bh[4][2];
#pragma unroll
            for (int mt = 0; mt < 4; mt++) {
                int row = wm + mt * 16 + (lane & 15);
                int cch = ks * 2 + (lane >> 4);
                uint32_t off = row * 128 + cch * 16;
                off ^= ((off >> 3) & 0x70);
                ldsm4(ah[mt], sbase + off);
                ldsm4(al[mt], sbase + GTILE + off);
            }
#pragma unroll
            for (int nt = 0; nt < 2; nt++) {
                int row = wn + nt * 16 + (lane & 15);
                int cch = ks * 2 + (lane >> 4);
                uint32_t off = row * 128 + cch * 16;
                off ^= ((off >> 3) & 0x70);
                uint32_t t[4];
                ldsm4(t, sbase + 2 * GTILE + off);
                bh[nt * 2][0] = t[0]; bh[nt * 2][1] = t[2];
                bh[nt * 2 + 1][0] = t[1]; bh[nt * 2 + 1][1] = t[3];
            }
#pragma unroll
            for (int mt = 0; mt < 4; mt++)
#pragma unroll
                for (int j = 0; j < 4; j++) {
                    mma16816(acc[mt][j], ah[mt], bh[j]);
                    mma16816(acc[mt][j], al[mt], bh[j]);
                }
        }
        __syncthreads();
    }

    if (MODE == 0 && n0 >= 2048) {
        // ---- V CTA: smem-staged transpose -> coalesced [b,h,d,t] stores ----
        constexpr int PITCH = 136;
        __half* svh = reinterpret_cast<__half*>(smem);
        int bidx = m0 >> 11, tbase = m0 & 2047;
#pragma unroll
        for (int hl = 0; hl < 2; hl++) {
            if (hl) __syncthreads();
#pragma unroll
            for (int mt = 0; mt < 4; mt++)
#pragma unroll
                for (int j = 0; j < 4; j++) {
                    int n = n0 + wn + j * 8 + (lane & 3) * 2;
                    if (((n >> 6) & 1) != hl) continue;
                    int dd = n & 63;
#pragma unroll
                    for (int half = 0; half < 2; half++) {
                        int tl = wm + mt * 16 + (lane >> 2) + half * 8;
                        svh[dd * PITCH + tl]       = __float2half_rn(acc[mt][j][half * 2]);
                        svh[(dd + 1) * PITCH + tl] = __float2half_rn(acc[mt][j][half * 2 + 1]);
                    }
                }
            __syncthreads();
            int h = ((n0 & 1023) >> 6) + hl;
            int bhn = bidx * 16 + h;
#pragma unroll
            for (int i = 0; i < 4; i++) {
                int id = tid + i * 256;          // 1024: 64 dd x 16 tc
                int dd = id >> 4, tc = id & 15;
                uint4 v = *reinterpret_cast<const uint4*>(svh + dd * PITCH + tc * 8);
                *reinterpret_cast<uint4*>(g_vth +
                    (((size_t)bhn * HD + dd) * Tt + tbase + tc * 8)) = v;
            }
        }
        return;
    }

#pragma unroll
    for (int mt = 0; mt < 4; mt++)
#pragma unroll
        for (int j = 0; j < 4; j++) {
            int n = n0 + wn + j * 8 + (lane & 3) * 2;
            int mA = m0 + wm + mt * 16 + (lane >> 2);
#pragma unroll
            for (int half = 0; half < 2; half++) {
                int m = mA + half * 8;
                float f0 = acc[mt][j][half * 2], f1 = acc[mt][j][half * 2 + 1];
                if (MODE == 0) {
                    int part = n >> 10, c1 = n & 1023, h = c1 >> 6, dd = c1 & 63;
                    int bidx = m >> 11, t = m & 2047;
                    int bhn = bidx * 16 + h;
                    size_t idx = ((size_t)bhn * Tt + t) * HD + dd;
                    if (part == 0) {
                        f0 *= 0.125f; f1 *= 0.125f;
                        uint32_t hp = packh(f0, f1), lp = packhlo(hp, f0, f1);
                        *reinterpret_cast<uint32_t*>(g_qh + idx) = hp;
                        *reinterpret_cast<uint32_t*>(g_ql + idx) = lp;
                    } else {
                        *reinterpret_cast<uint32_t*>(g_kh + idx) = packh(f0, f1);
                    }
                } else {
                    f0 += __ldg(bias + n);
                    f1 += __ldg(bias + n + 1);
                    float2 v = {f0, f1};
                    *reinterpret_cast<float2*>(out + (size_t)m * N + n) = v;
                }
            }
        }
}

// ---------------------------------------------------------------------------
// fp16 tensor-core flash attention. 128 q-rows x (b,h), 8 warps x 16 rows.
// S = (Qh+Ql)*Kh^T (2 mma); O += (Ph+Pl)*Vh (2 mma). Double-buffered stages.
// ---------------------------------------------------------------------------
__global__ __launch_bounds__(256, 1) void sa_attn_mma(const int* __restrict__ pad)
{
    extern __shared__ char smem[];
    __shared__ float pm[2][128];
    uint32_t sb = smem_u32(smem);
    int tid = threadIdx.x, lane = tid & 31, warp = tid >> 5;
    int qt = (int)gridDim.x - 1 - (int)blockIdx.x;   // big tiles first
    int bh = blockIdx.y, bb = bh >> 4, hh = bh & 15;
    int q0 = qt * 128;
    size_t kbase = (size_t)bh * Tt * HD;
    size_t vbase = (size_t)bh * HD * Tt;

    // ---- stage Q hi/lo, extract fragments ----
#pragma unroll
    for (int i = 0; i < 8; i++) {
        int id = tid + i * 256;            // 2048: arr x 128 rows x 8 chunks
        int arr = id >> 10, rem = id & 1023, row = rem >> 3, c = rem & 7;
        const __half* src = (arr ? g_ql : g_qh) + kbase + (size_t)(q0 + row) * HD + c * 8;
        cpasync16(sb + arr * 16384 + row * 128 + ((c ^ (row & 7)) << 4), src);
    }
    CP_COMMIT();
    CP_WAIT0();
    __syncthreads();
    uint32_t qh[4][4], ql[4][4];
#pragma unroll
    for (int ks = 0; ks < 4; ks++) {
        int row = warp * 16 + (lane & 15), cch = ks * 2 + (lane >> 4);
        uint32_t off = row * 128 + ((cch ^ (row & 7)) << 4);
        ldsm4(qh[ks], sb + off);
        ldsm4(ql[ks], sb + 16384 + off);
    }
    __syncthreads();

    auto load_stage = [&](int st, int kt) {
        uint32_t sbase = sb + st * ASTAGE;
        int k0 = kt * 128;
#pragma unroll
        for (int i = 0; i < 8; i++) {
            int id = tid + i * 256;        // 2048: Kh 1024 + Vth 1024 chunks
            int part = id >> 10, rem = id & 1023;
            if (part == 0) {
                int row = rem >> 3, c = rem & 7;
                const __half* src = g_kh + kbase + (size_t)(k0 + row) * HD + c * 8;
                cpasync16(sbase + row * 128 + ((c ^ (row & 7)) << 4), src);
            } else {
                int row = rem >> 4, c = rem & 15;
                const __half* src = g_vth + vbase + (size_t)row * Tt + k0 + c * 8;
                cpasync16(sbase + 16384 + row * 256 + ((c ^ (row & 7)) << 4), src);
            }
        }
        if (tid < 128) pm[st][tid] = pad[bb * Tt + k0 + tid] ? 0.0f : -1e30f;
    };

    float o[8][4];
#pragma unroll
    for (int i = 0; i < 8; i++)
#pragma unroll
        for (int e = 0; e < 4; e++) o[i][e] = 0.0f;
    float mrow[2] = {-1e30f, -1e30f}, lrow[2] = {0.0f, 0.0f};

    load_stage(0, 0);
    CP_COMMIT();

    for (int kt = 0; kt <= qt; kt++) {
        if (kt < qt) load_stage((kt + 1) & 1, kt + 1);
        CP_COMMIT();
        CP_WAIT1();
        __syncthreads();
        uint32_t sbase = sb + (kt & 1) * ASTAGE;

        // ---- S = Q K^T ----
        float s[16][4];
#pragma unroll
        for (int nt = 0; nt < 16; nt++)
#pragma unroll
            for (int e = 0; e < 4; e++) s[nt][e] = 0.0f;

#pragma unroll
        for (int ntp = 0; ntp < 8; ntp++) {
#pragma unroll
            for (int ks = 0; ks < 4; ks++) {
                int row = ntp * 16 + (lane & 15), cch = ks * 2 + (lane >> 4);
                uint32_t off = row * 128 + ((cch ^ (row & 7)) << 4);
                uint32_t t[4], kh0[2], kh1[2];
                ldsm4(t, sbase + off);
                kh0[0] = t[0]; kh0[1] = t[2]; kh1[0] = t[1]; kh1[1] = t[3];
                mma16816(s[2 * ntp], qh[ks], kh0);
                mma16816(s[2 * ntp], ql[ks], kh0);
                mma16816(s[2 * ntp + 1], qh[ks], kh1);
                mma16816(s[2 * ntp + 1], ql[ks], kh1);
            }
        }

        // ---- masks ----
        int c2 = 2 * (lane & 3);
#pragma unroll
        for (int nt = 0; nt < 16; nt++) {
            float m0v = pm[kt & 1][nt * 8 + c2];
            float m1v = pm[kt & 1][nt * 8 + c2 + 1];
            s[nt][0] += m0v; s[nt][1] += m1v; s[nt][2] += m0v; s[nt][3] += m1v;
        }
        if (kt == qt) {
            int r0 = warp * 16 + (lane >> 2), r1 = r0 + 8;
#pragma unroll
            for (int nt = 0; nt < 16; nt++) {
                int col0 = nt * 8 + c2;
                if (col0 > r0)     s[nt][0] = -1e30f;
                if (col0 + 1 > r0) s[nt][1] = -1e30f;
                if (col0 > r1)     s[nt][2] = -1e30f;
                if (col0 + 1 > r1) s[nt][3] = -1e30f;
            }
        }

        // ---- online softmax (2 rows per lane) ----
#pragma unroll
        for (int h2 = 0; h2 < 2; h2++) {
            float mt = -1e30f;
#pragma unroll
            for (int nt = 0; nt < 16; nt++)
                mt = fmaxf(mt, fmaxf(s[nt][2 * h2], s[nt][2 * h2 + 1]));
            mt = fmaxf(mt, __shfl_xor_sync(0xffffffffu, mt, 1));
            mt = fmaxf(mt, __shfl_xor_sync(0xffffffffu, mt, 2));
            float mnew = fmaxf(mrow[h2], mt);
            float alpha = __expf(mrow[h2] - mnew);
            float rs = 0.0f;
#pragma unroll
            for (int nt = 0; nt < 16; nt++) {
                s[nt][2 * h2]     = __expf(s[nt][2 * h2] - mnew);
                s[nt][2 * h2 + 1] = __expf(s[nt][2 * h2 + 1] - mnew);
                rs += s[nt][2 * h2] + s[nt][2 * h2 + 1];
            }
            rs += __shfl_xor_sync(0xffffffffu, rs, 1);
            rs += __shfl_xor_sync(0xffffffffu, rs, 2);
            lrow[h2] = lrow[h2] * alpha + rs;
            mrow[h2] = mnew;
#pragma unroll
            for (int dt = 0; dt < 8; dt++) {
                o[dt][2 * h2] *= alpha;
                o[dt][2 * h2 + 1] *= alpha;
            }
        }

        // ---- O += P V ----
#pragma unroll
        for (int ksp = 0; ksp < 8; ksp++) {
            int t0 = 2 * ksp, t1 = 2 * ksp + 1;
            uint32_t ah[4], al[4];
            ah[0] = packh(s[t0][0], s[t0][1]); al[0] = packhlo(ah[0], s[t0][0], s[t0][1]);
            ah[1] = packh(s[t0][2], s[t0][3]); al[1] = packhlo(ah[1], s[t0][2], s[t0][3]);
            ah[2] = packh(s[t1][0], s[t1][1]); al[2] = packhlo(ah[2], s[t1][0], s[t1][1]);
            ah[3] = packh(s[t1][2], s[t1][3]); al[3] = packhlo(ah[3], s[t1][2], s[t1][3]);
#pragma unroll
            for (int ntv = 0; ntv < 4; ntv++) {
                int row = ntv * 16 + (lane & 15), cch = ksp * 2 + (lane >> 4);
                uint32_t off = row * 256 + ((cch ^ (row & 7)) << 4);
                uint32_t t[4], vh0[2], vh1[2];
                ldsm4(t, sbase + 16384 + off);
                vh0[0] = t[0]; vh0[1] = t[2]; vh1[0] = t[1]; vh1[1] = t[3];
                mma16816(o[2 * ntv], ah, vh0);
                mma16816(o[2 * ntv], al, vh0);
                mma16816(o[2 * ntv + 1], ah, vh1);
                mma16816(o[2 * ntv + 1], al, vh1);
            }
        }
        __syncthreads();
    }

    // ---- normalize, split, write y (fp16 hi/lo) ----
    float i0 = 1.0f / lrow[0], i1 = 1.0f / lrow[1];
    int r0 = bb * Tt + q0 + warp * 16 + (lane >> 2), r1 = r0 + 8;
#pragma unroll
    for (int dt = 0; dt < 8; dt++) {
        int col = hh * 64 + dt * 8 + 2 * (lane & 3);
        float f0 = o[dt][0] * i0, f1 = o[dt][1] * i0;
        uint32_t hp = packh(f0, f1), lp = packhlo(hp, f0, f1);
        *reinterpret_cast<uint32_t*>(gy_h + (size_t)r0 * Cc + col) = hp;
        *reinterpret_cast<uint32_t*>(gy_l + (size_t)r0 * Cc + col) = lp;
        float f2 = o[dt][2] * i1, f3 = o[dt][3] * i1;
        uint32_t hp2 = packh(f2, f3), lp2 = packhlo(hp2, f2, f3);
        *reinterpret_cast<uint32_t*>(gy_h + (size_t)r1 * Cc + col) = hp2;
        *reinterpret_cast<uint32_t*>(gy_l + (size_t)r1 * Cc + col) = lp2;
    }
}

// ---------------------------------------------------------------------------
extern "C" void kernel_launch(void* const* d_in, const int* in_sizes, int n_in,
                              void* d_out, int out_size)
{
    (void)in_sizes; (void)n_in; (void)out_size;
    const float* x      = (const float*)d_in[0];
    const int*   pad    = (const int*)d_in[1];
    const float* w_attn = (const float*)d_in[2];
    const float* w_proj = (const float*)d_in[3];
    const float* b_proj = (const float*)d_in[4];
    float* out = (float*)d_out;

    cudaFuncSetAttribute(sa_gemm_mma<0>, cudaFuncAttributeMaxDynamicSharedMemorySize, GSM_BYTES);
    cudaFuncSetAttribute(sa_gemm_mma<1>, cudaFuncAttributeMaxDynamicSharedMemorySize, GSM_BYTES);
    cudaFuncSetAttribute(sa_attn_mma,    cudaFuncAttributeMaxDynamicSharedMemorySize, ASM_BYTES);

    void *pxh, *pxl, *pyh, *pyl, *pwah, *pwph;
    cudaGetSymbolAddress(&pxh, gx_h);  cudaGetSymbolAddress(&pxl, gx_l);
    cudaGetSymbolAddress(&pyh, gy_h);  cudaGetSymbolAddress(&pyl, gy_l);
    cudaGetSymbolAddress(&pwah, gwa_h); cudaGetSymbolAddress(&pwph, gwp_h);

    k_split<<<(BT * Kd / 4 + 255) / 256, 256>>>(
        (const float4*)x, (__half2*)pxh, (__half2*)pxl, BT * Kd / 4);
    k_splitT<<<dim3(3072 / 32, Kd / 32), dim3(32, 8)>>>(w_attn, (__half*)pwah, 3072);
    k_splitT<<<dim3(1024 / 32, Kd / 32), dim3(32, 8)>>>(w_proj, (__half*)pwph, 1024);

    sa_gemm_mma<0><<<dim3(3072 / 128, BT / 128), 256, GSM_BYTES>>>(
        (const __half*)pxh, (const __half*)pxl, (const __half*)pwah,
        nullptr, nullptr, 3072);

    sa_attn_mma<<<dim3(Tt / 128, Bb * Hh), 256, ASM_BYTES>>>(pad);

    sa_gemm_mma<1><<<dim3(1024 / 128, BT / 128), 256, GSM_BYTES>>>(
        (const __half*)pyh, (const __half*)pyl, (const __half*)pwph,
        b_proj, out, 1024);
}